// round 2
// baseline (speedup 1.0000x reference)
#include <cuda_runtime.h>
#include <cuda_bf16.h>

// ===========================================================================
// Shapes (fixed by dataset):
//  p0 (4,256,64,64)  p1 (4,512,32,32)  p2 (4,1024,16,16)
//  w1 (256,258) b1(256)  w2 (512,514) b2(512)  w3 (1024,1026) b3(1024)
//  C  (1792,4096)
//  out = [ score (4,200,64,64) | PHI[:, :896] (4,896,64,64) ]  fp32
// ===========================================================================

// ------------------------- device scratch ----------------------------------
__device__ float g_pool1[4 * 256 * 4096];
__device__ float g_pool2[4 * 512 * 1024];
__device__ float g_pool3[4 * 1024 * 256];
__device__ float g_low1[4 * 4096 * 256];   // [b][pos][o]
__device__ float g_low2[4 * 1024 * 512];
__device__ float g_low3[4 * 256 * 1024];
__device__ float g_phi[(size_t)4 * 4096 * 1792];          // [b][pos][k] fp32
__device__ __nv_bfloat16 g_phib[(size_t)4 * 4096 * 1792]; // bf16 copy
__device__ __nv_bfloat16 g_cb[(size_t)4096 * 1792];       // C^T bf16 [n][k]
__device__ float g_feats[4 * 4096];
__device__ float g_cents[4096];
__device__ float g_cpart[14][4096];
__device__ float g_S[(size_t)4 * 4096 * 4096];            // dist values

// ------------------------- helpers -----------------------------------------
__device__ __forceinline__ unsigned sptr(const void* p) {
    return (unsigned)__cvta_generic_to_shared(p);
}
__device__ __forceinline__ void cp_async16(unsigned dst, const void* src) {
    asm volatile("cp.async.cg.shared.global [%0], [%1], 16;\n"
                 :: "r"(dst), "l"(__cvta_generic_to_global(src)));
}
__device__ __forceinline__ void ldsm_x4(unsigned& r0, unsigned& r1,
                                        unsigned& r2, unsigned& r3, unsigned a) {
    asm volatile("ldmatrix.sync.aligned.m8n8.x4.shared.b16 {%0,%1,%2,%3}, [%4];\n"
                 : "=r"(r0), "=r"(r1), "=r"(r2), "=r"(r3) : "r"(a));
}
__device__ __forceinline__ void mma16816(float* c, const unsigned* a,
                                         unsigned b0, unsigned b1) {
    asm volatile(
        "mma.sync.aligned.m16n8k16.row.col.f32.bf16.bf16.f32 "
        "{%0,%1,%2,%3}, {%4,%5,%6,%7}, {%8,%9}, {%0,%1,%2,%3};\n"
        : "+f"(c[0]), "+f"(c[1]), "+f"(c[2]), "+f"(c[3])
        : "r"(a[0]), "r"(a[1]), "r"(a[2]), "r"(a[3]), "r"(b0), "r"(b1));
}

// ------------------------- 1) 3x3 avg pool (pad 1, /9) ----------------------
__global__ void pool_kernel(const float* __restrict__ x, int level, int C, int H) {
    float* out = (level == 0) ? g_pool1 : (level == 1) ? g_pool2 : g_pool3;
    int W = H;
    int i = blockIdx.x * 256 + threadIdx.x;       // grid sized exactly
    int wq = i % W;
    int h  = (i / W) % H;
    int bc = i / (W * H);
    const float* base = x + (size_t)bc * H * W;
    float s = 0.f;
#pragma unroll
    for (int dy = -1; dy <= 1; dy++) {
        int hh = h + dy;
        if (hh < 0 || hh >= H) continue;
#pragma unroll
        for (int dx = -1; dx <= 1; dx++) {
            int ww = wq + dx;
            if (ww < 0 || ww >= W) continue;
            s += base[hh * W + ww];
        }
    }
    out[i] = s * (1.f / 9.f);
}

// ------------------------- 2) fp32 CoordConv GEMM ---------------------------
// out[b][pos][n] = sum_c pooled[b][c][pos]*w[n][c] + w[n][Cl]*xg + w[n][Cl+1]*yg + b[n]
// M = positions (128 tile), N = out channels (128 tile), BK = 16.
__global__ __launch_bounds__(256) void conv_kernel(int level, int Cl, int HW, int W,
                                                   const float* __restrict__ wt,
                                                   const float* __restrict__ bias) {
    const float* pooled = (level == 0) ? g_pool1 : (level == 1) ? g_pool2 : g_pool3;
    float* outp         = (level == 0) ? g_low1  : (level == 1) ? g_low2  : g_low3;
    __shared__ __align__(16) float As[16][128];
    __shared__ __align__(16) float Bs[16][132];

    int t  = threadIdx.x;
    int tx = t & 15, ty = t >> 4;
    int n0 = blockIdx.x * 128;
    int m0 = blockIdx.y * 128;
    int b  = blockIdx.z;
    int ldw = Cl + 2;
    const float* Abase = pooled + (size_t)b * Cl * HW + m0;

    float acc[8][8];
#pragma unroll
    for (int i = 0; i < 8; i++)
#pragma unroll
        for (int j = 0; j < 8; j++) acc[i][j] = 0.f;

    for (int k0 = 0; k0 < Cl; k0 += 16) {
        {   // A tile: 16 k-rows x 128 contiguous positions
            int kk = t >> 4, m = (t & 15) * 8;
            const float* src = Abase + (size_t)(k0 + kk) * HW + m;
            *(float4*)&As[kk][m]     = *(const float4*)(src);
            *(float4*)&As[kk][m + 4] = *(const float4*)(src + 4);
        }
        {   // W tile transposed: Bs[kk][n] = w[n0+n][k0+kk]
            int n = t >> 1, half = t & 1;
            const float* src = wt + (size_t)(n0 + n) * ldw + k0 + half * 8;
#pragma unroll
            for (int j = 0; j < 8; j++) Bs[half * 8 + j][n] = src[j];
        }
        __syncthreads();
#pragma unroll
        for (int kk = 0; kk < 16; kk++) {
            float a[8], c[8];
            *(float4*)&a[0] = *(float4*)&As[kk][ty * 8];
            *(float4*)&a[4] = *(float4*)&As[kk][ty * 8 + 4];
            *(float4*)&c[0] = *(float4*)&Bs[kk][tx * 8];
            *(float4*)&c[4] = *(float4*)&Bs[kk][tx * 8 + 4];
#pragma unroll
            for (int i = 0; i < 8; i++)
#pragma unroll
                for (int j = 0; j < 8; j++) acc[i][j] = fmaf(a[i], c[j], acc[i][j]);
        }
        __syncthreads();
    }
    // epilogue: coord channels + bias
    float inv = 2.f / (float)(W - 1);
#pragma unroll
    for (int i = 0; i < 8; i++) {
        int pos = m0 + ty * 8 + i;
        int h = pos / W, w = pos % W;
        float xg = inv * w - 1.f;
        float yg = inv * h - 1.f;
#pragma unroll
        for (int j = 0; j < 8; j++) {
            int n = n0 + tx * 8 + j;
            const float* wr = wt + (size_t)n * ldw + Cl;
            float v = acc[i][j] + wr[0] * xg + wr[1] * yg + bias[n];
            outp[((size_t)b * HW + pos) * Cl + n] = v;
        }
    }
}

// ------------------------- 3) resize + assemble PHI -------------------------
// Bilinear (half-pixel, edge-clamped == jax normalized triangle for upsample).
__device__ __forceinline__ void taps(float f, int lim, int& i0, int& i1, float& wf) {
    float tf = floorf(f);
    wf = f - tf;
    int ti = (int)tf;
    i0 = min(lim, max(0, ti));
    i1 = min(lim, max(0, ti + 1));
}

__global__ void assemble_kernel() {
    int blk = blockIdx.x;            // b*4096 + pos
    int pos = blk & 4095;
    int b   = blk >> 12;
    int h = pos >> 6, w = pos & 63;

    // level-1 taps (32x32)
    int y10, y11, x10, x11; float wy1, wx1;
    taps(0.5f * h - 0.25f, 31, y10, y11, wy1);
    taps(0.5f * w - 0.25f, 31, x10, x11, wx1);
    // level-2 taps (16x16)
    int y20, y21, x20, x21; float wy2, wx2;
    taps(0.25f * h - 0.375f, 15, y20, y21, wy2);
    taps(0.25f * w - 0.375f, 15, x20, x21, wx2);

    size_t dst = (size_t)blk * 1792;
#pragma unroll
    for (int it = 0; it < 7; it++) {
        int k = it * 256 + threadIdx.x;
        float v;
        if (k < 256) {
            v = g_low1[(size_t)blk * 256 + k];
        } else if (k < 768) {
            int o = k - 256;
            const float* base = g_low2 + (size_t)b * 1024 * 512 + o;
            float v00 = base[(size_t)(y10 * 32 + x10) * 512];
            float v01 = base[(size_t)(y10 * 32 + x11) * 512];
            float v10 = base[(size_t)(y11 * 32 + x10) * 512];
            float v11 = base[(size_t)(y11 * 32 + x11) * 512];
            float va = v00 + wx1 * (v01 - v00);
            float vb = v10 + wx1 * (v11 - v10);
            v = va + wy1 * (vb - va);
        } else {
            int o = k - 768;
            const float* base = g_low3 + (size_t)b * 256 * 1024 + o;
            float v00 = base[(size_t)(y20 * 16 + x20) * 1024];
            float v01 = base[(size_t)(y20 * 16 + x21) * 1024];
            float v10 = base[(size_t)(y21 * 16 + x20) * 1024];
            float v11 = base[(size_t)(y21 * 16 + x21) * 1024];
            float va = v00 + wx2 * (v01 - v00);
            float vb = v10 + wx2 * (v11 - v10);
            v = va + wy2 * (vb - va);
        }
        g_phi[dst + k]  = v;
        g_phib[dst + k] = __float2bfloat16(v);
    }
}

// transpose PHI[:, :896] -> out2 [b][k][pos]
__global__ void phi_transpose_kernel(float* __restrict__ out2) {
    __shared__ float t[32][33];
    int k0 = blockIdx.x * 32;   // 28 tiles (896)
    int p0 = blockIdx.y * 32;   // 128 tiles (4096)
    int b  = blockIdx.z;
    int tx = threadIdx.x, ty = threadIdx.y;  // (32,8)
#pragma unroll
    for (int i = 0; i < 4; i++) {
        int p = p0 + ty + 8 * i;
        t[ty + 8 * i][tx] = g_phi[((size_t)(b * 4096 + p)) * 1792 + k0 + tx];
    }
    __syncthreads();
#pragma unroll
    for (int i = 0; i < 4; i++) {
        int k = k0 + ty + 8 * i;
        out2[(size_t)b * 896 * 4096 + (size_t)k * 4096 + p0 + tx] = t[tx][ty + 8 * i];
    }
}

// feats[b*4096+pos] = |phi row|^2  (one warp per row)
__global__ void feats_kernel() {
    int warp = threadIdx.x >> 5, lane = threadIdx.x & 31;
    int row = blockIdx.x * 8 + warp;
    const float* base = g_phi + (size_t)row * 1792;
    float s = 0.f;
    for (int i = lane; i < 1792; i += 32) { float v = base[i]; s = fmaf(v, v, s); }
#pragma unroll
    for (int o = 16; o; o >>= 1) s += __shfl_xor_sync(0xffffffffu, s, o);
    if (lane == 0) g_feats[row] = s;
}

// ------------------------- 4) C preparation ---------------------------------
__global__ void cents_part_kernel(const float* __restrict__ C) {
    int n  = blockIdx.x * 256 + threadIdx.x;
    int kb = blockIdx.y;
    float s = 0.f;
    for (int k = kb * 128; k < kb * 128 + 128; k++) {
        float v = C[(size_t)k * 4096 + n];
        s = fmaf(v, v, s);
    }
    g_cpart[kb][n] = s;
}
__global__ void cents_reduce_kernel() {
    int n = blockIdx.x * 256 + threadIdx.x;
    float s = 0.f;
#pragma unroll
    for (int i = 0; i < 14; i++) s += g_cpart[i][n];
    g_cents[n] = s;
}
// transpose-convert C [k][n] fp32 -> g_cb [n][k] bf16
__global__ void cconv_kernel(const float* __restrict__ C) {
    __shared__ float t[32][33];
    int n0 = blockIdx.x * 32;   // 128
    int k0 = blockIdx.y * 32;   // 56
    int tx = threadIdx.x, ty = threadIdx.y;  // (32,8)
#pragma unroll
    for (int i = 0; i < 4; i++)
        t[ty + 8 * i][tx] = C[(size_t)(k0 + ty + 8 * i) * 4096 + n0 + tx];
    __syncthreads();
#pragma unroll
    for (int i = 0; i < 4; i++)
        g_cb[(size_t)(n0 + ty + 8 * i) * 1792 + k0 + tx] =
            __float2bfloat16(t[tx][ty + 8 * i]);
}

// ------------------------- 5) distance GEMM (bf16 HMMA) ---------------------
// dist[b][m][n] = sqrt(feats[b][m] + cents[n] - 2 * phi.C)
__global__ __launch_bounds__(256, 2) void dist_kernel() {
    __shared__ __align__(16) __nv_bfloat16 sA[2][128][40];
    __shared__ __align__(16) __nv_bfloat16 sB[2][128][40];
    const int b  = blockIdx.z;
    const int m0 = blockIdx.y * 128;
    const int n0 = blockIdx.x * 128;
    const int tid  = threadIdx.x;
    const int warp = tid >> 5, lane = tid & 31;
    const int wm = warp >> 1, wn = warp & 1;   // 4x2 warp grid: 32m x 64n per warp

    const __nv_bfloat16* Ag = g_phib + ((size_t)b * 4096 + m0) * 1792;
    const __nv_bfloat16* Bg = g_cb + (size_t)n0 * 1792;

    float acc[2][8][4];
#pragma unroll
    for (int i = 0; i < 2; i++)
#pragma unroll
        for (int j = 0; j < 8; j++)
#pragma unroll
            for (int q = 0; q < 4; q++) acc[i][j][q] = 0.f;

    auto load_tile = [&](int s, int it) {
        int k0 = it * 32;
#pragma unroll
        for (int c = 0; c < 2; c++) {
            int ch  = tid + 256 * c;
            int row = ch >> 2;
            int kc  = (ch & 3) * 8;
            cp_async16(sptr(&sA[s][row][kc]), Ag + (size_t)row * 1792 + k0 + kc);
            cp_async16(sptr(&sB[s][row][kc]), Bg + (size_t)row * 1792 + k0 + kc);
        }
    };

    const int NIT = 56;   // 1792 / 32
    load_tile(0, 0); asm volatile("cp.async.commit_group;\n");
    load_tile(1, 1); asm volatile("cp.async.commit_group;\n");
    asm volatile("cp.async.wait_group 1;\n");
    __syncthreads();

    for (int it = 0; it < NIT; it++) {
        int s = it & 1;
#pragma unroll
        for (int kk = 0; kk < 2; kk++) {
            unsigned a[2][4];
#pragma unroll
            for (int mi = 0; mi < 2; mi++) {
                unsigned ad = sptr(&sA[s][wm * 32 + mi * 16 + (lane & 15)]
                                      [kk * 16 + (lane >> 4) * 8]);
                ldsm_x4(a[mi][0], a[mi][1], a[mi][2], a[mi][3], ad);
            }
            unsigned bf[4][4];
#pragma unroll
            for (int nq = 0; nq < 4; nq++) {
                unsigned ad = sptr(&sB[s][wn * 64 + nq * 16 + (lane & 15)]
                                      [kk * 16 + (lane >> 4) * 8]);
                ldsm_x4(bf[nq][0], bf[nq][1], bf[nq][2], bf[nq][3], ad);
            }
#pragma unroll
            for (int mi = 0; mi < 2; mi++)
#pragma unroll
                for (int nj = 0; nj < 8; nj++) {
                    unsigned b0 = (nj & 1) ? bf[nj >> 1][1] : bf[nj >> 1][0];
                    unsigned b1 = (nj & 1) ? bf[nj >> 1][3] : bf[nj >> 1][2];
                    mma16816(acc[mi][nj], a[mi], b0, b1);
                }
        }
        __syncthreads();
        if (it + 2 < NIT) {
            load_tile(s, it + 2);
            asm volatile("cp.async.commit_group;\n");
            asm volatile("cp.async.wait_group 1;\n");
        } else {
            asm volatile("cp.async.wait_group 0;\n");
        }
        __syncthreads();
    }

    // epilogue: dist = sqrt(feats + cents - 2*acc)
    const float* fr = g_feats + b * 4096 + m0;
    size_t outbase = ((size_t)b * 4096 + m0) * 4096 + n0;
#pragma unroll
    for (int mi = 0; mi < 2; mi++) {
        int r0 = wm * 32 + mi * 16 + (lane >> 2);
        float f0 = fr[r0], f1 = fr[r0 + 8];
#pragma unroll
        for (int nj = 0; nj < 8; nj++) {
            int c0 = wn * 64 + nj * 8 + (lane & 3) * 2;
            float ce0 = g_cents[n0 + c0], ce1 = g_cents[n0 + c0 + 1];
            float d0 = sqrtf(fmaxf(f0 + ce0 - 2.f * acc[mi][nj][0], 0.f));
            float d1 = sqrtf(fmaxf(f0 + ce1 - 2.f * acc[mi][nj][1], 0.f));
            float d2 = sqrtf(fmaxf(f1 + ce0 - 2.f * acc[mi][nj][2], 0.f));
            float d3 = sqrtf(fmaxf(f1 + ce1 - 2.f * acc[mi][nj][3], 0.f));
            *(float2*)&g_S[outbase + (size_t)r0 * 4096 + c0]       = make_float2(d0, d1);
            *(float2*)&g_S[outbase + (size_t)(r0 + 8) * 4096 + c0] = make_float2(d2, d3);
        }
    }
}

// ------------------------- 6) exact top-200 (sorted) ------------------------
// Radix-select on float bits (monotone for positives), warp-private hists,
// compact 200, bitonic sort 256, write score[b][j][pos].
__global__ __launch_bounds__(256) void topk_kernel(float* __restrict__ score) {
    __shared__ unsigned wh[8][256];
    __shared__ unsigned hist[256];
    __shared__ float sel[256];
    __shared__ int s_bin, s_need, s_cntA, s_cntB;

    int tid  = threadIdx.x;
    int warp = tid >> 5;
    int row  = blockIdx.x;              // b*4096 + pos
    const float* src = g_S + (size_t)row * 4096;

    unsigned u[16];
#pragma unroll
    for (int j = 0; j < 16; j++) u[j] = __float_as_uint(src[j * 256 + tid]);

    unsigned prefix = 0, pmask = 0;
    int need = 200;
#pragma unroll
    for (int pass = 0; pass < 4; pass++) {
        int shift = 24 - pass * 8;
#pragma unroll
        for (int w = 0; w < 8; w++) wh[w][tid] = 0;
        __syncthreads();
#pragma unroll
        for (int j = 0; j < 16; j++)
            if ((u[j] & pmask) == prefix)
                atomicAdd(&wh[warp][(u[j] >> shift) & 255], 1u);
        __syncthreads();
        unsigned tot = 0;
#pragma unroll
        for (int w = 0; w < 8; w++) tot += wh[w][tid];
        hist[tid] = tot;
        __syncthreads();
        if (tid == 0) {
            int cum = 0, bin = 0;
            for (; bin < 256; bin++) {
                int c = (int)hist[bin];
                if (cum + c >= need) break;
                cum += c;
            }
            s_bin = bin; s_need = need - cum;
        }
        __syncthreads();
        prefix |= ((unsigned)s_bin) << shift;
        pmask  |= 255u << shift;
        need = s_need;
        __syncthreads();
    }
    // prefix == bits of the 200th smallest value T; need = #ties to include
    int L = 200 - need;
    if (tid == 0) { s_cntA = 0; s_cntB = 0; }
    sel[tid] = __int_as_float(0x7f800000);   // +inf padding
    __syncthreads();
#pragma unroll
    for (int j = 0; j < 16; j++) {
        unsigned k = u[j];
        if (k < prefix) {
            int p = atomicAdd(&s_cntA, 1);
            sel[p] = __uint_as_float(k);
        } else if (k == prefix) {
            int p = atomicAdd(&s_cntB, 1);
            if (p < need) sel[L + p] = __uint_as_float(k);
        }
    }
    __syncthreads();

    // bitonic sort 256 ascending
    for (int kk = 2; kk <= 256; kk <<= 1)
        for (int jj = kk >> 1; jj > 0; jj >>= 1) {
            int ixj = tid ^ jj;
            if (ixj > tid) {
                bool up = ((tid & kk) == 0);
                float x = sel[tid], y = sel[ixj];
                if ((x > y) == up) { sel[tid] = y; sel[ixj] = x; }
            }
            __syncthreads();
        }

    if (tid < 200) {
        int b = row >> 12, pos = row & 4095;
        score[((size_t)b * 200 + tid) * 4096 + pos] = sel[tid];
    }
}

// ------------------------- launch ------------------------------------------
extern "C" void kernel_launch(void* const* d_in, const int* in_sizes, int n_in,
                              void* d_out, int out_size) {
    const float* p0 = (const float*)d_in[0];
    const float* p1 = (const float*)d_in[1];
    const float* p2 = (const float*)d_in[2];
    // d_in[3] = label (unused), d_in[4] = mask (unused)
    const float* w1 = (const float*)d_in[5];
    const float* b1 = (const float*)d_in[6];
    const float* w2 = (const float*)d_in[7];
    const float* b2 = (const float*)d_in[8];
    const float* w3 = (const float*)d_in[9];
    const float* b3 = (const float*)d_in[10];
    const float* C  = (const float*)d_in[11];

    float* score = (float*)d_out;
    float* out2  = (float*)d_out + (size_t)4 * 200 * 4096;

    // C preparation (independent of pyramid)
    cents_part_kernel<<<dim3(16, 14), 256>>>(C);
    cents_reduce_kernel<<<16, 256>>>();
    cconv_kernel<<<dim3(128, 56), dim3(32, 8)>>>(C);

    // pools
    pool_kernel<<<4 * 256 * 4096 / 256, 256>>>(p0, 0, 256, 64);
    pool_kernel<<<4 * 512 * 1024 / 256, 256>>>(p1, 1, 512, 32);
    pool_kernel<<<4 * 1024 * 256 / 256, 256>>>(p2, 2, 1024, 16);

    // CoordConv GEMMs (M = positions, N = out channels = Cl)
    conv_kernel<<<dim3(2, 32, 4), 256>>>(0, 256, 4096, 64, w1, b1);
    conv_kernel<<<dim3(4, 8, 4), 256>>>(1, 512, 1024, 32, w2, b2);
    conv_kernel<<<dim3(8, 2, 4), 256>>>(2, 1024, 256, 16, w3, b3);

    // resize + concat -> PHI (fp32 + bf16)
    assemble_kernel<<<4 * 4096, 256>>>();

    // second output: PHI[:, :896] transposed to [b][k][pos]
    phi_transpose_kernel<<<dim3(28, 128, 4), dim3(32, 8)>>>(out2);

    // row norms
    feats_kernel<<<2048, 256>>>();

    // distances
    dist_kernel<<<dim3(32, 32, 4), 256>>>();

    // top-200 sorted ascending
    topk_kernel<<<4 * 4096, 256>>>(score);
}

// round 4
// speedup vs baseline: 1.1986x; 1.1986x over previous
#include <cuda_runtime.h>
#include <cuda_bf16.h>
#include <cstdint>

// ===========================================================================
// Shapes (fixed by dataset):
//  p0 (4,256,64,64)  p1 (4,512,32,32)  p2 (4,1024,16,16)
//  w1 (256,258) b1(256)  w2 (512,514) b2(512)  w3 (1024,1026) b3(1024)
//  C  (1792,4096)
//  out = [ score (4,200,64,64) | PHI[:, :896] (4,896,64,64) ]  fp32
// ===========================================================================

// ------------------------- device scratch ----------------------------------
__device__ float g_pool1[4 * 256 * 4096];
__device__ float g_pool2[4 * 512 * 1024];
__device__ float g_pool3[4 * 1024 * 256];
__device__ float g_low1[4 * 4096 * 256];   // [b][pos][o]
__device__ float g_low2[4 * 1024 * 512];
__device__ float g_low3[4 * 256 * 1024];
__device__ float g_phi[(size_t)4 * 4096 * 1792];              // fp32 PHI [row][k]
__device__ __align__(16) char g_phiq[(size_t)4 * 4096 * 1792]; // int8 PHI
__device__ __align__(16) char g_cq[(size_t)4096 * 1792];       // int8 C^T [n][k]
__device__ float g_feats[4 * 4096];
__device__ float g_sa[4 * 4096];          // per-phi-row quant scale
__device__ float g_cents[4096];
__device__ float g_sb[4096];              // per-centroid quant scale
__device__ float g_cpart[14][4096];
__device__ float g_cmaxp[14][4096];
__device__ __align__(16) float g_S[(size_t)4 * 4096 * 4096];   // dist values

// ------------------------- helpers -----------------------------------------
__device__ __forceinline__ unsigned sptr(const void* p) {
    return (unsigned)__cvta_generic_to_shared(p);
}
__device__ __forceinline__ void cp_async16(unsigned dst, const void* src) {
    asm volatile("cp.async.cg.shared.global [%0], [%1], 16;\n"
                 :: "r"(dst), "l"(__cvta_generic_to_global(src)));
}
__device__ __forceinline__ void cp_commit() {
    asm volatile("cp.async.commit_group;\n");
}
template <int N>
__device__ __forceinline__ void cp_wait() {
    asm volatile("cp.async.wait_group %0;\n" :: "n"(N));
}
__device__ __forceinline__ void ldsm_x4(unsigned& r0, unsigned& r1,
                                        unsigned& r2, unsigned& r3, unsigned a) {
    asm volatile("ldmatrix.sync.aligned.m8n8.x4.shared.b16 {%0,%1,%2,%3}, [%4];\n"
                 : "=r"(r0), "=r"(r1), "=r"(r2), "=r"(r3) : "r"(a));
}
__device__ __forceinline__ void mma16832(int* c, const unsigned* a,
                                         unsigned b0, unsigned b1) {
    asm volatile(
        "mma.sync.aligned.m16n8k32.row.col.s32.s8.s8.s32 "
        "{%0,%1,%2,%3}, {%4,%5,%6,%7}, {%8,%9}, {%0,%1,%2,%3};\n"
        : "+r"(c[0]), "+r"(c[1]), "+r"(c[2]), "+r"(c[3])
        : "r"(a[0]), "r"(a[1]), "r"(a[2]), "r"(a[3]), "r"(b0), "r"(b1));
}
__device__ __forceinline__ char quant8(float v, float inv) {
    int q = __float2int_rn(v * inv);
    q = max(-127, min(127, q));
    return (char)q;
}

// ------------------------- 1) 3x3 avg pool (pad 1, /9) ----------------------
__global__ void pool_kernel(const float* __restrict__ x, int level, int C, int H) {
    float* out = (level == 0) ? g_pool1 : (level == 1) ? g_pool2 : g_pool3;
    int W = H;
    int i = blockIdx.x * 256 + threadIdx.x;
    int wq = i % W;
    int h  = (i / W) % H;
    int bc = i / (W * H);
    const float* base = x + (size_t)bc * H * W;
    float s = 0.f;
#pragma unroll
    for (int dy = -1; dy <= 1; dy++) {
        int hh = h + dy;
        if (hh < 0 || hh >= H) continue;
#pragma unroll
        for (int dx = -1; dx <= 1; dx++) {
            int ww = wq + dx;
            if (ww < 0 || ww >= W) continue;
            s += base[hh * W + ww];
        }
    }
    out[i] = s * (1.f / 9.f);
}

// ------------------------- 2) fp32 CoordConv GEMM (all 3 levels, 1 launch) --
// out[b][pos][n] = sum_c pooled[b][c][pos]*w[n][c] + coord terms + bias
// tiles: 128 pos x 128 ch, BK=16.  448 CTAs total.
__global__ __launch_bounds__(256) void conv_all_kernel(
        const float* __restrict__ w1, const float* __restrict__ b1,
        const float* __restrict__ w2, const float* __restrict__ b2,
        const float* __restrict__ w3, const float* __restrict__ b3) {
    __shared__ __align__(16) float As[16][128];
    __shared__ __align__(16) float Bs[16][132];

    int bid = blockIdx.x;
    int Cl, HW, W, b, m0, n0;
    const float *pooled, *wt, *bias;
    float* outp;
    if (bid < 256) {              // level 0: n-tiles 2, m-tiles 32, b 4
        Cl = 256; HW = 4096; W = 64;
        pooled = g_pool1; outp = g_low1; wt = w1; bias = b1;
        n0 = (bid & 1) * 128; m0 = ((bid >> 1) & 31) * 128; b = bid >> 6;
    } else if (bid < 384) {       // level 1: n 4, m 8, b 4
        int l = bid - 256;
        Cl = 512; HW = 1024; W = 32;
        pooled = g_pool2; outp = g_low2; wt = w2; bias = b2;
        n0 = (l & 3) * 128; m0 = ((l >> 2) & 7) * 128; b = l >> 5;
    } else {                      // level 2: n 8, m 2, b 4
        int l = bid - 384;
        Cl = 1024; HW = 256; W = 16;
        pooled = g_pool3; outp = g_low3; wt = w3; bias = b3;
        n0 = (l & 7) * 128; m0 = ((l >> 3) & 1) * 128; b = l >> 4;
    }
    int t  = threadIdx.x;
    int tx = t & 15, ty = t >> 4;
    int ldw = Cl + 2;
    const float* Abase = pooled + (size_t)b * Cl * HW + m0;

    float acc[8][8];
#pragma unroll
    for (int i = 0; i < 8; i++)
#pragma unroll
        for (int j = 0; j < 8; j++) acc[i][j] = 0.f;

    for (int k0 = 0; k0 < Cl; k0 += 16) {
        {
            int kk = t >> 4, m = (t & 15) * 8;
            const float* src = Abase + (size_t)(k0 + kk) * HW + m;
            *(float4*)&As[kk][m]     = *(const float4*)(src);
            *(float4*)&As[kk][m + 4] = *(const float4*)(src + 4);
        }
        {
            int n = t >> 1, half = t & 1;
            const float* src = wt + (size_t)(n0 + n) * ldw + k0 + half * 8;
#pragma unroll
            for (int j = 0; j < 8; j++) Bs[half * 8 + j][n] = src[j];
        }
        __syncthreads();
#pragma unroll
        for (int kk = 0; kk < 16; kk++) {
            float a[8], c[8];
            *(float4*)&a[0] = *(float4*)&As[kk][ty * 8];
            *(float4*)&a[4] = *(float4*)&As[kk][ty * 8 + 4];
            *(float4*)&c[0] = *(float4*)&Bs[kk][tx * 8];
            *(float4*)&c[4] = *(float4*)&Bs[kk][tx * 8 + 4];
#pragma unroll
            for (int i = 0; i < 8; i++)
#pragma unroll
                for (int j = 0; j < 8; j++) acc[i][j] = fmaf(a[i], c[j], acc[i][j]);
        }
        __syncthreads();
    }
    float inv = 2.f / (float)(W - 1);
#pragma unroll
    for (int i = 0; i < 8; i++) {
        int pos = m0 + ty * 8 + i;
        int h = pos / W, w = pos % W;
        float xg = inv * w - 1.f;
        float yg = inv * h - 1.f;
#pragma unroll
        for (int j = 0; j < 8; j++) {
            int n = n0 + tx * 8 + j;
            const float* wr = wt + (size_t)n * ldw + Cl;
            float v = acc[i][j] + wr[0] * xg + wr[1] * yg + bias[n];
            outp[((size_t)b * HW + pos) * Cl + n] = v;
        }
    }
}

// ------------------------- 3) resize + assemble PHI + feats + quantize ------
__device__ __forceinline__ void taps(float f, int lim, int& i0, int& i1, float& wf) {
    float tf = floorf(f);
    wf = f - tf;
    int ti = (int)tf;
    i0 = min(lim, max(0, ti));
    i1 = min(lim, max(0, ti + 1));
}

__global__ __launch_bounds__(256) void assemble_kernel() {
    __shared__ float red_s[8], red_m[8];
    __shared__ float s_inv;
    int blk = blockIdx.x;            // b*4096 + pos
    int pos = blk & 4095;
    int b   = blk >> 12;
    int h = pos >> 6, w = pos & 63;
    int tid = threadIdx.x, lane = tid & 31, wid = tid >> 5;

    int y10, y11, x10, x11; float wy1, wx1;
    taps(0.5f * h - 0.25f, 31, y10, y11, wy1);
    taps(0.5f * w - 0.25f, 31, x10, x11, wx1);
    int y20, y21, x20, x21; float wy2, wx2;
    taps(0.25f * h - 0.375f, 15, y20, y21, wy2);
    taps(0.25f * w - 0.375f, 15, x20, x21, wx2);

    float v[7];
    float ss = 0.f, amax = 0.f;
#pragma unroll
    for (int it = 0; it < 7; it++) {
        int k = it * 256 + tid;
        float val;
        if (k < 256) {
            val = g_low1[(size_t)blk * 256 + k];
        } else if (k < 768) {
            int o = k - 256;
            const float* base = g_low2 + (size_t)b * 1024 * 512 + o;
            float v00 = base[(size_t)(y10 * 32 + x10) * 512];
            float v01 = base[(size_t)(y10 * 32 + x11) * 512];
            float v10 = base[(size_t)(y11 * 32 + x10) * 512];
            float v11 = base[(size_t)(y11 * 32 + x11) * 512];
            float va = v00 + wx1 * (v01 - v00);
            float vb = v10 + wx1 * (v11 - v10);
            val = va + wy1 * (vb - va);
        } else {
            int o = k - 768;
            const float* base = g_low3 + (size_t)b * 256 * 1024 + o;
            float v00 = base[(size_t)(y20 * 16 + x20) * 1024];
            float v01 = base[(size_t)(y20 * 16 + x21) * 1024];
            float v10 = base[(size_t)(y21 * 16 + x20) * 1024];
            float v11 = base[(size_t)(y21 * 16 + x21) * 1024];
            float va = v00 + wx2 * (v01 - v00);
            float vb = v10 + wx2 * (v11 - v10);
            val = va + wy2 * (vb - va);
        }
        v[it] = val;
        ss = fmaf(val, val, ss);
        amax = fmaxf(amax, fabsf(val));
    }
#pragma unroll
    for (int o = 16; o; o >>= 1) {
        ss += __shfl_xor_sync(0xffffffffu, ss, o);
        amax = fmaxf(amax, __shfl_xor_sync(0xffffffffu, amax, o));
    }
    if (lane == 0) { red_s[wid] = ss; red_m[wid] = amax; }
    __syncthreads();
    if (tid == 0) {
        float S = 0.f, M = 0.f;
#pragma unroll
        for (int i = 0; i < 8; i++) { S += red_s[i]; M = fmaxf(M, red_m[i]); }
        g_feats[blk] = S;
        float sc = fmaxf(M, 1e-20f) * (1.f / 127.f);
        g_sa[blk] = sc;
        s_inv = 1.f / sc;
    }
    __syncthreads();
    float inv = s_inv;
    size_t dst = (size_t)blk * 1792;
#pragma unroll
    for (int it = 0; it < 7; it++) {
        int k = it * 256 + tid;
        g_phi[dst + k]  = v[it];
        g_phiq[dst + k] = quant8(v[it], inv);
    }
}

// transpose PHI[:, :896] -> out2 [b][k][pos]
__global__ void phi_transpose_kernel(float* __restrict__ out2) {
    __shared__ float t[32][33];
    int k0 = blockIdx.x * 32;
    int p0 = blockIdx.y * 32;
    int b  = blockIdx.z;
    int tx = threadIdx.x, ty = threadIdx.y;
#pragma unroll
    for (int i = 0; i < 4; i++) {
        int p = p0 + ty + 8 * i;
        t[ty + 8 * i][tx] = g_phi[((size_t)(b * 4096 + p)) * 1792 + k0 + tx];
    }
    __syncthreads();
#pragma unroll
    for (int i = 0; i < 4; i++) {
        int k = k0 + ty + 8 * i;
        out2[(size_t)b * 896 * 4096 + (size_t)k * 4096 + p0 + tx] = t[tx][ty + 8 * i];
    }
}

// ------------------------- 4) C preparation ---------------------------------
__global__ void cents_part_kernel(const float* __restrict__ C) {
    int n  = blockIdx.x * 256 + threadIdx.x;
    int kb = blockIdx.y;
    float s = 0.f, m = 0.f;
    for (int k = kb * 128; k < kb * 128 + 128; k++) {
        float v = C[(size_t)k * 4096 + n];
        s = fmaf(v, v, s);
        m = fmaxf(m, fabsf(v));
    }
    g_cpart[kb][n] = s;
    g_cmaxp[kb][n] = m;
}
__global__ void cents_reduce_kernel() {
    int n = blockIdx.x * 256 + threadIdx.x;
    float s = 0.f, m = 0.f;
#pragma unroll
    for (int i = 0; i < 14; i++) { s += g_cpart[i][n]; m = fmaxf(m, g_cmaxp[i][n]); }
    g_cents[n] = s;
    g_sb[n] = fmaxf(m, 1e-20f) * (1.f / 127.f);
}
// transpose-quantize C [k][n] fp32 -> g_cq [n][k] int8
__global__ void cconv_kernel(const float* __restrict__ C) {
    __shared__ float t[32][33];
    int n0 = blockIdx.x * 32;
    int k0 = blockIdx.y * 32;
    int tx = threadIdx.x, ty = threadIdx.y;
#pragma unroll
    for (int i = 0; i < 4; i++)
        t[ty + 8 * i][tx] = C[(size_t)(k0 + ty + 8 * i) * 4096 + n0 + tx];
    __syncthreads();
#pragma unroll
    for (int i = 0; i < 4; i++) {
        int n = n0 + ty + 8 * i;
        float inv = 1.f / g_sb[n];
        g_cq[(size_t)n * 1792 + k0 + tx] = quant8(t[tx][ty + 8 * i], inv);
    }
}

// ------------------------- 5) distance GEMM (int8 mma.sync) -----------------
// dist[b][m][n] = sqrt(feats[m] + cents[n] - 2*sa[m]*sb[n]*acc_s32)
// CTA: 128x128 tile, k-stage 64 int8 (64 bytes/row), 2-stage cp.async.
__global__ __launch_bounds__(256, 2) void dist_kernel() {
    __shared__ __align__(16) char sA[2][128][80];
    __shared__ __align__(16) char sB[2][128][80];
    const int b  = blockIdx.z;
    const int m0 = blockIdx.y * 128;
    const int n0 = blockIdx.x * 128;
    const int tid  = threadIdx.x;
    const int warp = tid >> 5, lane = tid & 31;
    const int wm = warp >> 1, wn = warp & 1;   // 4x2 warps: 32m x 64n each

    const char* Ag = g_phiq + ((size_t)b * 4096 + m0) * 1792;
    const char* Bg = g_cq + (size_t)n0 * 1792;

    int acc[2][8][4];
#pragma unroll
    for (int i = 0; i < 2; i++)
#pragma unroll
        for (int j = 0; j < 8; j++)
#pragma unroll
            for (int q = 0; q < 4; q++) acc[i][j][q] = 0;

    auto load_tile = [&](int s, int it) {
        int k0 = it * 64;
#pragma unroll
        for (int c = 0; c < 2; c++) {
            int ch  = tid + 256 * c;
            int row = ch >> 2;
            int kc  = (ch & 3) * 16;
            cp_async16(sptr(&sA[s][row][kc]), Ag + (size_t)row * 1792 + k0 + kc);
            cp_async16(sptr(&sB[s][row][kc]), Bg + (size_t)row * 1792 + k0 + kc);
        }
    };

    const int NIT = 28;   // 1792 / 64
    load_tile(0, 0); cp_commit();
    load_tile(1, 1); cp_commit();
    cp_wait<1>();
    __syncthreads();

    for (int it = 0; it < NIT; it++) {
        int s = it & 1;
#pragma unroll
        for (int kk = 0; kk < 2; kk++) {
            unsigned a[2][4];
#pragma unroll
            for (int mi = 0; mi < 2; mi++) {
                unsigned ad = sptr(&sA[s][wm * 32 + mi * 16 + (lane & 15)]
                                      [kk * 32 + (lane >> 4) * 16]);
                ldsm_x4(a[mi][0], a[mi][1], a[mi][2], a[mi][3], ad);
            }
            unsigned bf[4][4];
#pragma unroll
            for (int nq = 0; nq < 4; nq++) {
                unsigned ad = sptr(&sB[s][wn * 64 + nq * 16 + (lane & 15)]
                                      [kk * 32 + (lane >> 4) * 16]);
                ldsm_x4(bf[nq][0], bf[nq][1], bf[nq][2], bf[nq][3], ad);
            }
#pragma unroll
            for (int mi = 0; mi < 2; mi++)
#pragma unroll
                for (int nj = 0; nj < 8; nj++) {
                    unsigned b0 = (nj & 1) ? bf[nj >> 1][1] : bf[nj >> 1][0];
                    unsigned b1 = (nj & 1) ? bf[nj >> 1][3] : bf[nj >> 1][2];
                    mma16832(acc[mi][nj], a[mi], b0, b1);
                }
        }
        __syncthreads();
        if (it + 2 < NIT) {
            load_tile(s, it + 2);
            cp_commit();
            cp_wait<1>();
        } else {
            cp_wait<0>();
        }
        __syncthreads();
    }

    // epilogue
    const float* fr = g_feats + b * 4096 + m0;
    const float* sr = g_sa + b * 4096 + m0;
    size_t outbase = ((size_t)b * 4096 + m0) * 4096 + n0;
#pragma unroll
    for (int mi = 0; mi < 2; mi++) {
        int r0 = wm * 32 + mi * 16 + (lane >> 2);
        float f0 = fr[r0], f1 = fr[r0 + 8];
        float sa0 = sr[r0] * 2.f, sa1 = sr[r0 + 8] * 2.f;
#pragma unroll
        for (int nj = 0; nj < 8; nj++) {
            int c0 = wn * 64 + nj * 8 + (lane & 3) * 2;
            float ce0 = g_cents[n0 + c0], ce1 = g_cents[n0 + c0 + 1];
            float sb0 = g_sb[n0 + c0], sb1 = g_sb[n0 + c0 + 1];
            float d0 = sqrtf(fmaxf(f0 + ce0 - sa0 * sb0 * (float)acc[mi][nj][0], 0.f));
            float d1 = sqrtf(fmaxf(f0 + ce1 - sa0 * sb1 * (float)acc[mi][nj][1], 0.f));
            float d2 = sqrtf(fmaxf(f1 + ce0 - sa1 * sb0 * (float)acc[mi][nj][2], 0.f));
            float d3 = sqrtf(fmaxf(f1 + ce1 - sa1 * sb1 * (float)acc[mi][nj][3], 0.f));
            *(float2*)&g_S[outbase + (size_t)r0 * 4096 + c0]       = make_float2(d0, d1);
            *(float2*)&g_S[outbase + (size_t)(r0 + 8) * 4096 + c0] = make_float2(d2, d3);
        }
    }
}

// ------------------------- 6) exact top-200 (sorted) ------------------------
// Adaptive-base radix select: 4096 linear bins over [lo, lo+4096w), narrow
// until w==1 (exact uint threshold). 2 iterations typical for this data.
__global__ __launch_bounds__(256) void topk_kernel(float* __restrict__ score) {
    __shared__ unsigned hist[4096];
    __shared__ unsigned warpscan[8];
    __shared__ unsigned sred_mn[8], sred_mx[8];
    __shared__ unsigned s_B, s_k;
    __shared__ float sel[256];
    __shared__ int s_cntA, s_cntB;

    const int tid = threadIdx.x, lane = tid & 31, wid = tid >> 5;
    int row = blockIdx.x;              // b*4096 + pos
    const float* src = g_S + (size_t)row * 4096;

    unsigned u[16];
#pragma unroll
    for (int j = 0; j < 16; j++) u[j] = __float_as_uint(src[j * 256 + tid]);

    // block min/max (positive floats: uint order == float order)
    unsigned mn = u[0], mx = u[0];
#pragma unroll
    for (int j = 1; j < 16; j++) { mn = min(mn, u[j]); mx = max(mx, u[j]); }
#pragma unroll
    for (int o = 16; o; o >>= 1) {
        mn = min(mn, __shfl_xor_sync(0xffffffffu, mn, o));
        mx = max(mx, __shfl_xor_sync(0xffffffffu, mx, o));
    }
    if (lane == 0) { sred_mn[wid] = mn; sred_mx[wid] = mx; }
    __syncthreads();
#pragma unroll
    for (int i = 0; i < 8; i++) {
        mn = min(mn, sred_mn[i]);
        mx = max(mx, sred_mx[i]);
    }

    unsigned lo = mn;
    unsigned w  = (mx - mn) / 4096u + 1u;
    unsigned k  = 200;                  // rank needed within current window
    while (true) {
#pragma unroll
        for (int i = 0; i < 16; i++) hist[tid + 256 * i] = 0;
        __syncthreads();
#pragma unroll
        for (int j = 0; j < 16; j++) {
            unsigned x = u[j];
            if (x >= lo) {
                unsigned bin = (x - lo) / w;
                if (bin < 4096u) atomicAdd(&hist[bin], 1u);
            }
        }
        __syncthreads();
        // segment sums (16 bins/thread) + block scan
        unsigned base = tid * 16, s = 0;
#pragma unroll
        for (int i = 0; i < 16; i++) s += hist[base + i];
        unsigned inc = s;
#pragma unroll
        for (int o = 1; o < 32; o <<= 1) {
            unsigned n = __shfl_up_sync(0xffffffffu, inc, o);
            if (lane >= o) inc += n;
        }
        if (lane == 31) warpscan[wid] = inc;
        __syncthreads();
        unsigned woff = 0;
        for (int i = 0; i < wid; i++) woff += warpscan[i];
        unsigned incl = inc + woff, excl = incl - s;
        if (k > excl && k <= incl) {      // this thread's 16 bins hold rank k
            unsigned c = excl;
            for (int i = 0; i < 16; i++) {
                unsigned hcnt = hist[base + i];
                if (c + hcnt >= k) { s_B = base + i; s_k = k - c; break; }
                c += hcnt;
            }
        }
        __syncthreads();
        lo = lo + s_B * w;
        k  = s_k;
        if (w == 1u) break;
        w = w / 4096u + 1u;
        __syncthreads();
    }

    // exact threshold: T = lo, take L = 200-k strictly below + k equal
    unsigned T = lo;
    int need = (int)k;
    int L = 200 - need;
    if (tid == 0) { s_cntA = 0; s_cntB = 0; }
    sel[tid] = __int_as_float(0x7f800000);
    __syncthreads();
#pragma unroll
    for (int j = 0; j < 16; j++) {
        unsigned x = u[j];
        if (x < T) {
            int p = atomicAdd(&s_cntA, 1);
            sel[p] = __uint_as_float(x);
        } else if (x == T) {
            int p = atomicAdd(&s_cntB, 1);
            if (p < need) sel[L + p] = __uint_as_float(x);
        }
    }
    __syncthreads();

    // bitonic sort 256 ascending
    for (int kk = 2; kk <= 256; kk <<= 1)
        for (int jj = kk >> 1; jj > 0; jj >>= 1) {
            int ixj = tid ^ jj;
            if (ixj > tid) {
                bool up = ((tid & kk) == 0);
                float x = sel[tid], y = sel[ixj];
                if ((x > y) == up) { sel[tid] = y; sel[ixj] = x; }
            }
            __syncthreads();
        }

    if (tid < 200) {
        int b = row >> 12, pos = row & 4095;
        score[((size_t)b * 200 + tid) * 4096 + pos] = sel[tid];
    }
}

// ------------------------- launch ------------------------------------------
extern "C" void kernel_launch(void* const* d_in, const int* in_sizes, int n_in,
                              void* d_out, int out_size) {
    const float* p0 = (const float*)d_in[0];
    const float* p1 = (const float*)d_in[1];
    const float* p2 = (const float*)d_in[2];
    const float* w1 = (const float*)d_in[5];
    const float* b1 = (const float*)d_in[6];
    const float* w2 = (const float*)d_in[7];
    const float* b2 = (const float*)d_in[8];
    const float* w3 = (const float*)d_in[9];
    const float* b3 = (const float*)d_in[10];
    const float* C  = (const float*)d_in[11];

    float* score = (float*)d_out;
    float* out2  = (float*)d_out + (size_t)4 * 200 * 4096;

    // C preparation (independent of pyramid)
    cents_part_kernel<<<dim3(16, 14), 256>>>(C);
    cents_reduce_kernel<<<16, 256>>>();
    cconv_kernel<<<dim3(128, 56), dim3(32, 8)>>>(C);

    // pools
    pool_kernel<<<4 * 256 * 4096 / 256, 256>>>(p0, 0, 256, 64);
    pool_kernel<<<4 * 512 * 1024 / 256, 256>>>(p1, 1, 512, 32);
    pool_kernel<<<4 * 1024 * 256 / 256, 256>>>(p2, 2, 1024, 16);

    // all three CoordConv GEMMs in one launch (448 CTAs)
    conv_all_kernel<<<448, 256>>>(w1, b1, w2, b2, w3, b3);

    // resize + concat -> PHI (fp32 + int8) + feats + row scales
    assemble_kernel<<<4 * 4096, 256>>>();

    // second output: PHI[:, :896] transposed to [b][k][pos]
    phi_transpose_kernel<<<dim3(28, 128, 4), dim3(32, 8)>>>(out2);

    // distances (int8 tensor cores)
    dist_kernel<<<dim3(32, 32, 4), 256>>>();

    // top-200 sorted ascending
    topk_kernel<<<4 * 4096, 256>>>(score);
}

// round 6
// speedup vs baseline: 1.2436x; 1.0376x over previous
#include <cuda_runtime.h>
#include <cuda_bf16.h>
#include <cstdint>

// ===========================================================================
// Shapes (fixed by dataset):
//  p0 (4,256,64,64)  p1 (4,512,32,32)  p2 (4,1024,16,16)
//  w1 (256,258) b1(256)  w2 (512,514) b2(512)  w3 (1024,1026) b3(1024)
//  C  (1792,4096)
//  out = [ score (4,200,64,64) | PHI[:, :896] (4,896,64,64) ]  fp32
// ===========================================================================

// ------------------------- device scratch ----------------------------------
__device__ float g_pool1[4 * 256 * 4096];
__device__ float g_pool2[4 * 512 * 1024];
__device__ float g_pool3[4 * 1024 * 256];
__device__ float g_low1[4 * 4096 * 256];   // [b][pos][o]
__device__ float g_low2[4 * 1024 * 512];
__device__ float g_low3[4 * 256 * 1024];
__device__ float g_phi[(size_t)4 * 4096 * 1792];              // fp32 PHI [row][k]
__device__ __align__(16) char g_phiq[(size_t)4 * 4096 * 1792]; // int8 PHI
__device__ __align__(16) char g_cq[(size_t)4096 * 1792];       // int8 C^T [n][k]
__device__ float g_feats[4 * 4096];
__device__ float g_sa[4 * 4096];          // per-phi-row quant scale
__device__ float g_cents[4096];
__device__ float g_sb[4096];              // per-centroid quant scale
__device__ __align__(16) float g_S[(size_t)4 * 4096 * 4096];   // dist^2 values

// ------------------------- helpers -----------------------------------------
__device__ __forceinline__ unsigned sptr(const void* p) {
    return (unsigned)__cvta_generic_to_shared(p);
}
__device__ __forceinline__ void cp_async16(unsigned dst, const void* src) {
    asm volatile("cp.async.cg.shared.global [%0], [%1], 16;\n"
                 :: "r"(dst), "l"(__cvta_generic_to_global(src)));
}
__device__ __forceinline__ void cp_commit() {
    asm volatile("cp.async.commit_group;\n");
}
template <int N>
__device__ __forceinline__ void cp_wait() {
    asm volatile("cp.async.wait_group %0;\n" :: "n"(N));
}
__device__ __forceinline__ void ldsm_x4(unsigned& r0, unsigned& r1,
                                        unsigned& r2, unsigned& r3, unsigned a) {
    asm volatile("ldmatrix.sync.aligned.m8n8.x4.shared.b16 {%0,%1,%2,%3}, [%4];\n"
                 : "=r"(r0), "=r"(r1), "=r"(r2), "=r"(r3) : "r"(a));
}
__device__ __forceinline__ void mma16832(int* c, const unsigned* a,
                                         unsigned b0, unsigned b1) {
    asm volatile(
        "mma.sync.aligned.m16n8k32.row.col.s32.s8.s8.s32 "
        "{%0,%1,%2,%3}, {%4,%5,%6,%7}, {%8,%9}, {%0,%1,%2,%3};\n"
        : "+r"(c[0]), "+r"(c[1]), "+r"(c[2]), "+r"(c[3])
        : "r"(a[0]), "r"(a[1]), "r"(a[2]), "r"(a[3]), "r"(b0), "r"(b1));
}
__device__ __forceinline__ char quant8(float v, float inv) {
    int q = __float2int_rn(v * inv);
    q = max(-127, min(127, q));
    return (char)q;
}

// ------------------------- 1) 3x3 avg pool, all levels, one launch ----------
// sizes: L0 4*256*4096 = 4194304, L1 2097152, L2 1048576  (all pow2 mapping)
__global__ __launch_bounds__(256) void pool_all_kernel(
        const float* __restrict__ p0, const float* __restrict__ p1,
        const float* __restrict__ p2) {
    int i = blockIdx.x * 256 + threadIdx.x;
    const float* x;
    float* out;
    int logW, j;
    if (i < 4194304)      { x = p0; out = g_pool1; logW = 6; j = i; }
    else if (i < 6291456) { x = p1; out = g_pool2; logW = 5; j = i - 4194304; }
    else                  { x = p2; out = g_pool3; logW = 4; j = i - 6291456; }
    int W = 1 << logW;
    int w = j & (W - 1);
    int h = (j >> logW) & (W - 1);
    int bc = j >> (2 * logW);
    const float* base = x + ((size_t)bc << (2 * logW));
    float s = 0.f;
    if (h > 0 && h < W - 1 && w > 0 && w < W - 1) {
        const float* r0 = base + ((h - 1) << logW) + w;
        const float* r1 = base + (h << logW) + w;
        const float* r2 = base + ((h + 1) << logW) + w;
        s = r0[-1] + r0[0] + r0[1] + r1[-1] + r1[0] + r1[1] + r2[-1] + r2[0] + r2[1];
    } else {
#pragma unroll
        for (int dy = -1; dy <= 1; dy++) {
            int hh = h + dy;
            if (hh < 0 || hh >= W) continue;
#pragma unroll
            for (int dx = -1; dx <= 1; dx++) {
                int ww = w + dx;
                if (ww < 0 || ww >= W) continue;
                s += base[(hh << logW) + ww];
            }
        }
    }
    out[j] = s * (1.f / 9.f);
}

// ------------------------- 2) C norms + quant scales (one launch) -----------
// grid 16 x 1024 threads: n = blk*256 + (t&255), k-quarter = t>>8
__global__ __launch_bounds__(1024) void cents_kernel(const float* __restrict__ C) {
    __shared__ float ss[4][256], mm[4][256];
    int t = threadIdx.x;
    int nl = t & 255, q = t >> 8;
    int n = blockIdx.x * 256 + nl;
    float s = 0.f, m = 0.f;
    for (int k = q * 448; k < q * 448 + 448; k++) {
        float v = C[(size_t)k * 4096 + n];
        s = fmaf(v, v, s);
        m = fmaxf(m, fabsf(v));
    }
    ss[q][nl] = s; mm[q][nl] = m;
    __syncthreads();
    if (q == 0) {
        float S = ss[0][nl] + ss[1][nl] + ss[2][nl] + ss[3][nl];
        float M = fmaxf(fmaxf(mm[0][nl], mm[1][nl]), fmaxf(mm[2][nl], mm[3][nl]));
        g_cents[n] = S;
        g_sb[n] = fmaxf(M, 1e-20f) * (1.f / 127.f);
    }
}

// transpose-quantize C [k][n] fp32 -> g_cq [n][k] int8
__global__ void cconv_kernel(const float* __restrict__ C) {
    __shared__ float t[32][33];
    int n0 = blockIdx.x * 32;
    int k0 = blockIdx.y * 32;
    int tx = threadIdx.x, ty = threadIdx.y;
#pragma unroll
    for (int i = 0; i < 4; i++)
        t[ty + 8 * i][tx] = C[(size_t)(k0 + ty + 8 * i) * 4096 + n0 + tx];
    __syncthreads();
#pragma unroll
    for (int i = 0; i < 4; i++) {
        int n = n0 + ty + 8 * i;
        float inv = 1.f / g_sb[n];
        g_cq[(size_t)n * 1792 + k0 + tx] = quant8(t[tx][ty + 8 * i], inv);
    }
}

// ------------------------- 3) fp32 CoordConv GEMM (all 3 levels) ------------
// heavy level-2 blocks first for better wave packing.
__global__ __launch_bounds__(256) void conv_all_kernel(
        const float* __restrict__ w1, const float* __restrict__ b1,
        const float* __restrict__ w2, const float* __restrict__ b2,
        const float* __restrict__ w3, const float* __restrict__ b3) {
    __shared__ __align__(16) float As[16][128];
    __shared__ __align__(16) float Bs[16][132];

    int bid = blockIdx.x;
    int Cl, HW, W, b, m0, n0;
    const float *pooled, *wt, *bias;
    float* outp;
    if (bid < 64) {               // level 2: n 8, m 2, b 4
        Cl = 1024; HW = 256; W = 16;
        pooled = g_pool3; outp = g_low3; wt = w3; bias = b3;
        n0 = (bid & 7) * 128; m0 = ((bid >> 3) & 1) * 128; b = bid >> 4;
    } else if (bid < 192) {       // level 1: n 4, m 8, b 4
        int l = bid - 64;
        Cl = 512; HW = 1024; W = 32;
        pooled = g_pool2; outp = g_low2; wt = w2; bias = b2;
        n0 = (l & 3) * 128; m0 = ((l >> 2) & 7) * 128; b = l >> 5;
    } else {                      // level 0: n 2, m 32, b 4
        int l = bid - 192;
        Cl = 256; HW = 4096; W = 64;
        pooled = g_pool1; outp = g_low1; wt = w1; bias = b1;
        n0 = (l & 1) * 128; m0 = ((l >> 1) & 31) * 128; b = l >> 6;
    }
    int t  = threadIdx.x;
    int tx = t & 15, ty = t >> 4;
    int ldw = Cl + 2;
    const float* Abase = pooled + (size_t)b * Cl * HW + m0;

    float acc[8][8];
#pragma unroll
    for (int i = 0; i < 8; i++)
#pragma unroll
        for (int j = 0; j < 8; j++) acc[i][j] = 0.f;

    for (int k0 = 0; k0 < Cl; k0 += 16) {
        {
            int kk = t >> 4, m = (t & 15) * 8;
            const float* src = Abase + (size_t)(k0 + kk) * HW + m;
            *(float4*)&As[kk][m]     = *(const float4*)(src);
            *(float4*)&As[kk][m + 4] = *(const float4*)(src + 4);
        }
        {
            int n = t >> 1, half = t & 1;
            const float* src = wt + (size_t)(n0 + n) * ldw + k0 + half * 8;
#pragma unroll
            for (int j = 0; j < 8; j++) Bs[half * 8 + j][n] = src[j];
        }
        __syncthreads();
#pragma unroll
        for (int kk = 0; kk < 16; kk++) {
            float a[8], c[8];
            *(float4*)&a[0] = *(float4*)&As[kk][ty * 8];
            *(float4*)&a[4] = *(float4*)&As[kk][ty * 8 + 4];
            *(float4*)&c[0] = *(float4*)&Bs[kk][tx * 8];
            *(float4*)&c[4] = *(float4*)&Bs[kk][tx * 8 + 4];
#pragma unroll
            for (int i = 0; i < 8; i++)
#pragma unroll
                for (int j = 0; j < 8; j++) acc[i][j] = fmaf(a[i], c[j], acc[i][j]);
        }
        __syncthreads();
    }
    float inv = 2.f / (float)(W - 1);
#pragma unroll
    for (int i = 0; i < 8; i++) {
        int pos = m0 + ty * 8 + i;
        int h = pos / W, w = pos % W;
        float xg = inv * w - 1.f;
        float yg = inv * h - 1.f;
#pragma unroll
        for (int j = 0; j < 8; j++) {
            int n = n0 + tx * 8 + j;
            const float* wr = wt + (size_t)n * ldw + Cl;
            float v = acc[i][j] + wr[0] * xg + wr[1] * yg + bias[n];
            outp[((size_t)b * HW + pos) * Cl + n] = v;
        }
    }
}

// ------------------------- 4) resize + assemble PHI + feats + quantize ------
__device__ __forceinline__ void taps(float f, int lim, int& i0, int& i1, float& wf) {
    float tf = floorf(f);
    wf = f - tf;
    int ti = (int)tf;
    i0 = min(lim, max(0, ti));
    i1 = min(lim, max(0, ti + 1));
}

__global__ __launch_bounds__(256) void assemble_kernel() {
    __shared__ float red_s[8], red_m[8];
    __shared__ float s_inv;
    int blk = blockIdx.x;            // b*4096 + pos
    int pos = blk & 4095;
    int b   = blk >> 12;
    int h = pos >> 6, w = pos & 63;
    int tid = threadIdx.x, lane = tid & 31, wid = tid >> 5;

    int y10, y11, x10, x11; float wy1, wx1;
    taps(0.5f * h - 0.25f, 31, y10, y11, wy1);
    taps(0.5f * w - 0.25f, 31, x10, x11, wx1);
    int y20, y21, x20, x21; float wy2, wx2;
    taps(0.25f * h - 0.375f, 15, y20, y21, wy2);
    taps(0.25f * w - 0.375f, 15, x20, x21, wx2);

    float v[7];
    float ss = 0.f, amax = 0.f;
#pragma unroll
    for (int it = 0; it < 7; it++) {
        int k = it * 256 + tid;
        float val;
        if (k < 256) {
            val = g_low1[(size_t)blk * 256 + k];
        } else if (k < 768) {
            int o = k - 256;
            const float* base = g_low2 + (size_t)b * 1024 * 512 + o;
            float v00 = base[(size_t)(y10 * 32 + x10) * 512];
            float v01 = base[(size_t)(y10 * 32 + x11) * 512];
            float v10 = base[(size_t)(y11 * 32 + x10) * 512];
            float v11 = base[(size_t)(y11 * 32 + x11) * 512];
            float va = v00 + wx1 * (v01 - v00);
            float vb = v10 + wx1 * (v11 - v10);
            val = va + wy1 * (vb - va);
        } else {
            int o = k - 768;
            const float* base = g_low3 + (size_t)b * 256 * 1024 + o;
            float v00 = base[(size_t)(y20 * 16 + x20) * 1024];
            float v01 = base[(size_t)(y20 * 16 + x21) * 1024];
            float v10 = base[(size_t)(y21 * 16 + x20) * 1024];
            float v11 = base[(size_t)(y21 * 16 + x21) * 1024];
            float va = v00 + wx2 * (v01 - v00);
            float vb = v10 + wx2 * (v11 - v10);
            val = va + wy2 * (vb - va);
        }
        v[it] = val;
        ss = fmaf(val, val, ss);
        amax = fmaxf(amax, fabsf(val));
    }
#pragma unroll
    for (int o = 16; o; o >>= 1) {
        ss += __shfl_xor_sync(0xffffffffu, ss, o);
        amax = fmaxf(amax, __shfl_xor_sync(0xffffffffu, amax, o));
    }
    if (lane == 0) { red_s[wid] = ss; red_m[wid] = amax; }
    __syncthreads();
    if (tid == 0) {
        float S = 0.f, M = 0.f;
#pragma unroll
        for (int i = 0; i < 8; i++) { S += red_s[i]; M = fmaxf(M, red_m[i]); }
        g_feats[blk] = S;
        float sc = fmaxf(M, 1e-20f) * (1.f / 127.f);
        g_sa[blk] = sc;
        s_inv = 1.f / sc;
    }
    __syncthreads();
    float inv = s_inv;
    size_t dst = (size_t)blk * 1792;
#pragma unroll
    for (int it = 0; it < 7; it++) {
        int k = it * 256 + tid;
        g_phi[dst + k]  = v[it];
        g_phiq[dst + k] = quant8(v[it], inv);
    }
}

// transpose PHI[:, :896] -> out2 [b][k][pos]
__global__ void phi_transpose_kernel(float* __restrict__ out2) {
    __shared__ float t[32][33];
    int k0 = blockIdx.x * 32;
    int p0 = blockIdx.y * 32;
    int b  = blockIdx.z;
    int tx = threadIdx.x, ty = threadIdx.y;
#pragma unroll
    for (int i = 0; i < 4; i++) {
        int p = p0 + ty + 8 * i;
        t[ty + 8 * i][tx] = g_phi[((size_t)(b * 4096 + p)) * 1792 + k0 + tx];
    }
    __syncthreads();
#pragma unroll
    for (int i = 0; i < 4; i++) {
        int k = k0 + ty + 8 * i;
        out2[(size_t)b * 896 * 4096 + (size_t)k * 4096 + p0 + tx] = t[tx][ty + 8 * i];
    }
}

// ------------------------- 5) distance^2 GEMM (int8 mma.sync) ---------------
// dist2[b][m][n] = feats[m] + cents[n] - 2*sa[m]*sb[n]*acc_s32   (NO sqrt here)
// CTA 128x128, 4 warps (2x2), warp tile 64x64, k-stage 64B, 2-stage cp.async.
__global__ __launch_bounds__(128, 2) void dist_kernel() {
    __shared__ __align__(16) char sA[2][128][80];
    __shared__ __align__(16) char sB[2][128][80];
    const int b  = blockIdx.z;
    const int m0 = blockIdx.y * 128;
    const int n0 = blockIdx.x * 128;
    const int tid  = threadIdx.x;
    const int warp = tid >> 5, lane = tid & 31;
    const int wm = warp >> 1, wn = warp & 1;   // 2x2 warps: 64m x 64n each

    const char* Ag = g_phiq + ((size_t)b * 4096 + m0) * 1792;
    const char* Bg = g_cq + (size_t)n0 * 1792;

    int acc[4][8][4];
#pragma unroll
    for (int i = 0; i < 4; i++)
#pragma unroll
        for (int j = 0; j < 8; j++)
#pragma unroll
            for (int q = 0; q < 4; q++) acc[i][j][q] = 0;

    auto load_tile = [&](int s, int it) {
        int k0 = it * 64;
#pragma unroll
        for (int c = 0; c < 8; c++) {
            int ch  = c * 128 + tid;
            int row = ch >> 2;
            int kc  = (ch & 3) * 16;
            if (row < 128)
                cp_async16(sptr(&sA[s][row][kc]), Ag + (size_t)row * 1792 + k0 + kc);
            else
                cp_async16(sptr(&sB[s][row - 128][kc]),
                           Bg + (size_t)(row - 128) * 1792 + k0 + kc);
        }
    };

    const int NIT = 28;   // 1792 / 64
    load_tile(0, 0); cp_commit();
    load_tile(1, 1); cp_commit();
    cp_wait<1>();
    __syncthreads();

    for (int it = 0; it < NIT; it++) {
        int s = it & 1;
#pragma unroll
        for (int kk = 0; kk < 2; kk++) {
            unsigned a[4][4];
#pragma unroll
            for (int mi = 0; mi < 4; mi++) {
                unsigned ad = sptr(&sA[s][wm * 64 + mi * 16 + (lane & 15)]
                                      [kk * 32 + (lane >> 4) * 16]);
                ldsm_x4(a[mi][0], a[mi][1], a[mi][2], a[mi][3], ad);
            }
            unsigned bf[4][4];
#pragma unroll
            for (int nq = 0; nq < 4; nq++) {
                unsigned ad = sptr(&sB[s][wn * 64 + nq * 16 + (lane & 15)]
                                      [kk * 32 + (lane >> 4) * 16]);
                ldsm_x4(bf[nq][0], bf[nq][1], bf[nq][2], bf[nq][3], ad);
            }
#pragma unroll
            for (int mi = 0; mi < 4; mi++)
#pragma unroll
                for (int nj = 0; nj < 8; nj++) {
                    unsigned b0 = (nj & 1) ? bf[nj >> 1][1] : bf[nj >> 1][0];
                    unsigned b1 = (nj & 1) ? bf[nj >> 1][3] : bf[nj >> 1][2];
                    mma16832(acc[mi][nj], a[mi], b0, b1);
                }
        }
        __syncthreads();
        if (it + 2 < NIT) {
            load_tile(s, it + 2);
            cp_commit();
            cp_wait<1>();
        } else {
            cp_wait<0>();
        }
        __syncthreads();
    }

    // epilogue: store dist^2 (sqrt deferred to topk)
    const float* fr = g_feats + b * 4096 + m0;
    const float* sr = g_sa + b * 4096 + m0;
    size_t outbase = ((size_t)b * 4096 + m0) * 4096 + n0;
#pragma unroll
    for (int mi = 0; mi < 4; mi++) {
        int r0 = wm * 64 + mi * 16 + (lane >> 2);
        float f0 = fr[r0], f1 = fr[r0 + 8];
        float sa0 = sr[r0] * 2.f, sa1 = sr[r0 + 8] * 2.f;
#pragma unroll
        for (int nj = 0; nj < 8; nj++) {
            int c0 = wn * 64 + nj * 8 + (lane & 3) * 2;
            float ce0 = g_cents[n0 + c0], ce1 = g_cents[n0 + c0 + 1];
            float sb0 = g_sb[n0 + c0], sb1 = g_sb[n0 + c0 + 1];
            float d0 = fmaxf(f0 + ce0 - sa0 * sb0 * (float)acc[mi][nj][0], 0.f);
            float d1 = fmaxf(f0 + ce1 - sa0 * sb1 * (float)acc[mi][nj][1], 0.f);
            float d2 = fmaxf(f1 + ce0 - sa1 * sb0 * (float)acc[mi][nj][2], 0.f);
            float d3 = fmaxf(f1 + ce1 - sa1 * sb1 * (float)acc[mi][nj][3], 0.f);
            *(float2*)&g_S[outbase + (size_t)r0 * 4096 + c0]       = make_float2(d0, d1);
            *(float2*)&g_S[outbase + (size_t)(r0 + 8) * 4096 + c0] = make_float2(d2, d3);
        }
    }
}

// ------------------------- 6) exact top-200 (sorted), on dist^2 -------------
__global__ __launch_bounds__(256) void topk_kernel(float* __restrict__ score) {
    __shared__ unsigned hist[4096];
    __shared__ unsigned warpscan[8];
    __shared__ unsigned sred_mn[8], sred_mx[8];
    __shared__ unsigned s_B, s_k;
    __shared__ float sel[256];
    __shared__ int s_cntA, s_cntB;

    const int tid = threadIdx.x, lane = tid & 31, wid = tid >> 5;
    int row = blockIdx.x;              // b*4096 + pos
    const float* src = g_S + (size_t)row * 4096;

    unsigned u[16];
#pragma unroll
    for (int j = 0; j < 16; j++) u[j] = __float_as_uint(src[j * 256 + tid]);

    unsigned mn = u[0], mx = u[0];
#pragma unroll
    for (int j = 1; j < 16; j++) { mn = min(mn, u[j]); mx = max(mx, u[j]); }
#pragma unroll
    for (int o = 16; o; o >>= 1) {
        mn = min(mn, __shfl_xor_sync(0xffffffffu, mn, o));
        mx = max(mx, __shfl_xor_sync(0xffffffffu, mx, o));
    }
    if (lane == 0) { sred_mn[wid] = mn; sred_mx[wid] = mx; }
    __syncthreads();
#pragma unroll
    for (int i = 0; i < 8; i++) {
        mn = min(mn, sred_mn[i]);
        mx = max(mx, sred_mx[i]);
    }

    unsigned lo = mn;
    unsigned w  = (mx - mn) / 4096u + 1u;
    unsigned k  = 200;
    while (true) {
#pragma unroll
        for (int i = 0; i < 16; i++) hist[tid + 256 * i] = 0;
        __syncthreads();
#pragma unroll
        for (int j = 0; j < 16; j++) {
            unsigned x = u[j];
            if (x >= lo) {
                unsigned bin = (x - lo) / w;
                if (bin < 4096u) atomicAdd(&hist[bin], 1u);
            }
        }
        __syncthreads();
        unsigned base = tid * 16, s = 0;
#pragma unroll
        for (int i = 0; i < 16; i++) s += hist[base + i];
        unsigned inc = s;
#pragma unroll
        for (int o = 1; o < 32; o <<= 1) {
            unsigned n = __shfl_up_sync(0xffffffffu, inc, o);
            if (lane >= o) inc += n;
        }
        if (lane == 31) warpscan[wid] = inc;
        __syncthreads();
        unsigned woff = 0;
        for (int i = 0; i < wid; i++) woff += warpscan[i];
        unsigned incl = inc + woff, excl = incl - s;
        if (k > excl && k <= incl) {
            unsigned c = excl;
            for (int i = 0; i < 16; i++) {
                unsigned hcnt = hist[base + i];
                if (c + hcnt >= k) { s_B = base + i; s_k = k - c; break; }
                c += hcnt;
            }
        }
        __syncthreads();
        lo = lo + s_B * w;
        k  = s_k;
        if (w == 1u) break;
        w = w / 4096u + 1u;
        __syncthreads();
    }

    unsigned T = lo;
    int need = (int)k;
    int L = 200 - need;
    if (tid == 0) { s_cntA = 0; s_cntB = 0; }
    sel[tid] = __int_as_float(0x7f800000);
    __syncthreads();
#pragma unroll
    for (int j = 0; j < 16; j++) {
        unsigned x = u[j];
        if (x < T) {
            int p = atomicAdd(&s_cntA, 1);
            sel[p] = __uint_as_float(x);
        } else if (x == T) {
            int p = atomicAdd(&s_cntB, 1);
            if (p < need) sel[L + p] = __uint_as_float(x);
        }
    }
    __syncthreads();

    for (int kk = 2; kk <= 256; kk <<= 1)
        for (int jj = kk >> 1; jj > 0; jj >>= 1) {
            int ixj = tid ^ jj;
            if (ixj > tid) {
                bool up = ((tid & kk) == 0);
                float x = sel[tid], y = sel[ixj];
                if ((x > y) == up) { sel[tid] = y; sel[ixj] = x; }
            }
            __syncthreads();
        }

    if (tid < 200) {
        int b = row >> 12, pos = row & 4095;
        score[((size_t)b * 200 + tid) * 4096 + pos] = sqrtf(sel[tid]);
    }
}

// ------------------------- launch ------------------------------------------
extern "C" void kernel_launch(void* const* d_in, const int* in_sizes, int n_in,
                              void* d_out, int out_size) {
    const float* p0 = (const float*)d_in[0];
    const float* p1 = (const float*)d_in[1];
    const float* p2 = (const float*)d_in[2];
    const float* w1 = (const float*)d_in[5];
    const float* b1 = (const float*)d_in[6];
    const float* w2 = (const float*)d_in[7];
    const float* b2 = (const float*)d_in[8];
    const float* w3 = (const float*)d_in[9];
    const float* b3 = (const float*)d_in[10];
    const float* C  = (const float*)d_in[11];

    float* score = (float*)d_out;
    float* out2  = (float*)d_out + (size_t)4 * 200 * 4096;

    // launch order chosen so dist_kernel is launch #6 (ncu -s 5 -c 1 captures it)
    pool_all_kernel<<<28672, 256>>>(p0, p1, p2);          // 1
    cents_kernel<<<16, 1024>>>(C);                        // 2
    cconv_kernel<<<dim3(128, 56), dim3(32, 8)>>>(C);      // 3
    conv_all_kernel<<<448, 256>>>(w1, b1, w2, b2, w3, b3);// 4
    assemble_kernel<<<4 * 4096, 256>>>();                 // 5
    dist_kernel<<<dim3(32, 32, 4), 128>>>();              // 6
    phi_transpose_kernel<<<dim3(28, 128, 4), dim3(32, 8)>>>(out2); // 7
    topk_kernel<<<4 * 4096, 256>>>(score);                // 8
}

// round 7
// speedup vs baseline: 1.3711x; 1.1025x over previous
#include <cuda_runtime.h>
#include <cuda_bf16.h>
#include <cstdint>

// ===========================================================================
// Shapes (fixed by dataset):
//  p0 (4,256,64,64)  p1 (4,512,32,32)  p2 (4,1024,16,16)
//  w1 (256,258) b1(256)  w2 (512,514) b2(512)  w3 (1024,1026) b3(1024)
//  C  (1792,4096)
//  out = [ score (4,200,64,64) | PHI[:, :896] (4,896,64,64) ]  fp32
// ===========================================================================

// ------------------------- device scratch ----------------------------------
__device__ float g_pool1[4 * 256 * 4096];
__device__ float g_pool2[4 * 512 * 1024];
__device__ float g_pool3[4 * 1024 * 256];
__device__ float g_low1[4 * 4096 * 256];   // [b][pos][o]
__device__ float g_low2[4 * 1024 * 512];
__device__ float g_low3[4 * 256 * 1024];
__device__ float g_phi[(size_t)4 * 4096 * 1792];              // fp32 PHI [row][k]
__device__ __align__(16) char g_phiq[(size_t)4 * 4096 * 1792]; // int8 PHI
__device__ __align__(16) char g_cq[(size_t)4096 * 1792];       // int8 C^T [n][k]
__device__ float g_feats[4 * 4096];
__device__ float g_sa[4 * 4096];          // per-phi-row quant scale
__device__ float g_cents[4096];
__device__ float g_sb[4096];              // per-centroid quant scale
__device__ __align__(16) float g_S[(size_t)4 * 4096 * 4096];   // dist^2 values

// ------------------------- helpers -----------------------------------------
__device__ __forceinline__ unsigned sptr(const void* p) {
    return (unsigned)__cvta_generic_to_shared(p);
}
__device__ __forceinline__ void cp_async16(unsigned dst, const void* src) {
    asm volatile("cp.async.cg.shared.global [%0], [%1], 16;\n"
                 :: "r"(dst), "l"(__cvta_generic_to_global(src)));
}
__device__ __forceinline__ void cp_commit() {
    asm volatile("cp.async.commit_group;\n");
}
template <int N>
__device__ __forceinline__ void cp_wait() {
    asm volatile("cp.async.wait_group %0;\n" :: "n"(N));
}
__device__ __forceinline__ void ldsm_x4(unsigned& r0, unsigned& r1,
                                        unsigned& r2, unsigned& r3, unsigned a) {
    asm volatile("ldmatrix.sync.aligned.m8n8.x4.shared.b16 {%0,%1,%2,%3}, [%4];\n"
                 : "=r"(r0), "=r"(r1), "=r"(r2), "=r"(r3) : "r"(a));
}
__device__ __forceinline__ void mma16832(int* c, const unsigned* a,
                                         unsigned b0, unsigned b1) {
    asm volatile(
        "mma.sync.aligned.m16n8k32.row.col.s32.s8.s8.s32 "
        "{%0,%1,%2,%3}, {%4,%5,%6,%7}, {%8,%9}, {%0,%1,%2,%3};\n"
        : "+r"(c[0]), "+r"(c[1]), "+r"(c[2]), "+r"(c[3])
        : "r"(a[0]), "r"(a[1]), "r"(a[2]), "r"(a[3]), "r"(b0), "r"(b1));
}
__device__ __forceinline__ char quant8(float v, float inv) {
    int q = __float2int_rn(v * inv);
    q = max(-127, min(127, q));
    return (char)q;
}

// ------------------------- 1) 3x3 avg pool, all levels, one launch ----------
__global__ __launch_bounds__(256) void pool_all_kernel(
        const float* __restrict__ p0, const float* __restrict__ p1,
        const float* __restrict__ p2) {
    int i = blockIdx.x * 256 + threadIdx.x;
    const float* x;
    float* out;
    int logW, j;
    if (i < 4194304)      { x = p0; out = g_pool1; logW = 6; j = i; }
    else if (i < 6291456) { x = p1; out = g_pool2; logW = 5; j = i - 4194304; }
    else                  { x = p2; out = g_pool3; logW = 4; j = i - 6291456; }
    int W = 1 << logW;
    int w = j & (W - 1);
    int h = (j >> logW) & (W - 1);
    int bc = j >> (2 * logW);
    const float* base = x + ((size_t)bc << (2 * logW));
    float s = 0.f;
    if (h > 0 && h < W - 1 && w > 0 && w < W - 1) {
        const float* r0 = base + ((h - 1) << logW) + w;
        const float* r1 = base + (h << logW) + w;
        const float* r2 = base + ((h + 1) << logW) + w;
        s = r0[-1] + r0[0] + r0[1] + r1[-1] + r1[0] + r1[1] + r2[-1] + r2[0] + r2[1];
    } else {
#pragma unroll
        for (int dy = -1; dy <= 1; dy++) {
            int hh = h + dy;
            if (hh < 0 || hh >= W) continue;
#pragma unroll
            for (int dx = -1; dx <= 1; dx++) {
                int ww = w + dx;
                if (ww < 0 || ww >= W) continue;
                s += base[(hh << logW) + ww];
            }
        }
    }
    out[j] = s * (1.f / 9.f);
}

// ------------------------- 2) C prep: norms + scales + transpose-quantize ---
// 128 blocks x 256 thr. Block owns 32 n-columns.
__global__ __launch_bounds__(256) void cprep_kernel(const float* __restrict__ C) {
    __shared__ float ss[8][32], mm[8][32];
    __shared__ float sinv[32];
    __shared__ float t[32][33];
    int tid = threadIdx.x;
    int nl = tid & 31, kg = tid >> 5;      // warp kg handles k = kg mod 8
    int n0 = blockIdx.x * 32;

    // phase 1: per-column sum of squares + absmax
    float s = 0.f, m = 0.f;
    for (int k = kg; k < 1792; k += 8) {
        float v = C[(size_t)k * 4096 + n0 + nl];
        s = fmaf(v, v, s);
        m = fmaxf(m, fabsf(v));
    }
    ss[kg][nl] = s; mm[kg][nl] = m;
    __syncthreads();
    if (kg == 0) {
        float S = 0.f, M = 0.f;
#pragma unroll
        for (int i = 0; i < 8; i++) { S += ss[i][nl]; M = fmaxf(M, mm[i][nl]); }
        g_cents[n0 + nl] = S;
        float sc = fmaxf(M, 1e-20f) * (1.f / 127.f);
        g_sb[n0 + nl] = sc;
        sinv[nl] = 1.f / sc;
    }
    __syncthreads();

    // phase 2: transpose-quantize in 32k x 32n chunks
    int r  = tid >> 3;             // 0..31 : n index for writes
    int c0 = (tid & 7) * 4;        // k sub-offset
    float inv = sinv[r];
    for (int kc = 0; kc < 56; kc++) {
#pragma unroll
        for (int i = 0; i < 4; i++) {
            int kloc = kg * 4 + i;
            t[kloc][nl] = C[(size_t)(kc * 32 + kloc) * 4096 + n0 + nl];
        }
        __syncthreads();
        uchar4 pk;
        pk.x = (unsigned char)quant8(t[c0 + 0][r], inv);
        pk.y = (unsigned char)quant8(t[c0 + 1][r], inv);
        pk.z = (unsigned char)quant8(t[c0 + 2][r], inv);
        pk.w = (unsigned char)quant8(t[c0 + 3][r], inv);
        *(uchar4*)&g_cq[(size_t)(n0 + r) * 1792 + kc * 32 + c0] = pk;
        __syncthreads();
    }
}

// ------------------------- 3) fp32 CoordConv GEMM (all 3 levels) ------------
// CTA tile 128 pos x 64 ch, 256 thr, microtile 8x4. Level-2 blocks first.
__global__ __launch_bounds__(256) void conv_all_kernel(
        const float* __restrict__ w1, const float* __restrict__ b1,
        const float* __restrict__ w2, const float* __restrict__ b2,
        const float* __restrict__ w3, const float* __restrict__ b3) {
    __shared__ __align__(16) float As[16][128];
    __shared__ __align__(16) float Bs[16][68];

    int bid = blockIdx.x;
    int Cl, HW, W, b, m0, n0;
    const float *pooled, *wt, *bias;
    float* outp;
    if (bid < 128) {              // level 2: n 16, m 2, b 4
        Cl = 1024; HW = 256; W = 16;
        pooled = g_pool3; outp = g_low3; wt = w3; bias = b3;
        n0 = (bid & 15) * 64; m0 = ((bid >> 4) & 1) * 128; b = bid >> 5;
    } else if (bid < 384) {       // level 1: n 8, m 8, b 4
        int l = bid - 128;
        Cl = 512; HW = 1024; W = 32;
        pooled = g_pool2; outp = g_low2; wt = w2; bias = b2;
        n0 = (l & 7) * 64; m0 = ((l >> 3) & 7) * 128; b = l >> 6;
    } else {                      // level 0: n 4, m 32, b 4
        int l = bid - 384;
        Cl = 256; HW = 4096; W = 64;
        pooled = g_pool1; outp = g_low1; wt = w1; bias = b1;
        n0 = (l & 3) * 64; m0 = ((l >> 2) & 31) * 128; b = l >> 7;
    }
    int t  = threadIdx.x;
    int tx = t & 15, ty = t >> 4;          // tx: 4 n each, ty: 8 m each
    int ldw = Cl + 2;
    const float* Abase = pooled + (size_t)b * Cl * HW + m0;

    float acc[8][4];
#pragma unroll
    for (int i = 0; i < 8; i++)
#pragma unroll
        for (int j = 0; j < 4; j++) acc[i][j] = 0.f;

    for (int k0 = 0; k0 < Cl; k0 += 16) {
        {   // A tile: 16 k rows x 128 pos
            int kk = t >> 4, m = (t & 15) * 8;
            const float* src = Abase + (size_t)(k0 + kk) * HW + m;
            *(float4*)&As[kk][m]     = *(const float4*)(src);
            *(float4*)&As[kk][m + 4] = *(const float4*)(src + 4);
        }
        {   // B tile: Bs[kk][n] = w[n0+n][k0+kk];  thread: n = t>>2, 4 k's
            int n = t >> 2, q = t & 3;
            const float* src = wt + (size_t)(n0 + n) * ldw + k0 + q * 4;
#pragma unroll
            for (int j = 0; j < 4; j++) Bs[q * 4 + j][n] = src[j];
        }
        __syncthreads();
#pragma unroll
        for (int kk = 0; kk < 16; kk++) {
            float a[8], c[4];
            *(float4*)&a[0] = *(float4*)&As[kk][ty * 8];
            *(float4*)&a[4] = *(float4*)&As[kk][ty * 8 + 4];
            *(float4*)&c[0] = *(float4*)&Bs[kk][tx * 4];
#pragma unroll
            for (int i = 0; i < 8; i++)
#pragma unroll
                for (int j = 0; j < 4; j++) acc[i][j] = fmaf(a[i], c[j], acc[i][j]);
        }
        __syncthreads();
    }
    float inv = 2.f / (float)(W - 1);
#pragma unroll
    for (int i = 0; i < 8; i++) {
        int pos = m0 + ty * 8 + i;
        int h = pos / W, w = pos % W;
        float xg = inv * w - 1.f;
        float yg = inv * h - 1.f;
#pragma unroll
        for (int j = 0; j < 4; j++) {
            int n = n0 + tx * 4 + j;
            const float* wr = wt + (size_t)n * ldw + Cl;
            float v = acc[i][j] + wr[0] * xg + wr[1] * yg + bias[n];
            outp[((size_t)b * HW + pos) * Cl + n] = v;
        }
    }
}

// ------------------------- 4) resize + assemble PHI + feats + quantize ------
__device__ __forceinline__ void taps(float f, int lim, int& i0, int& i1, float& wf) {
    float tf = floorf(f);
    wf = f - tf;
    int ti = (int)tf;
    i0 = min(lim, max(0, ti));
    i1 = min(lim, max(0, ti + 1));
}

__global__ __launch_bounds__(256) void assemble_kernel() {
    __shared__ float red_s[8], red_m[8];
    __shared__ float s_inv;
    int blk = blockIdx.x;            // b*4096 + pos
    int pos = blk & 4095;
    int b   = blk >> 12;
    int h = pos >> 6, w = pos & 63;
    int tid = threadIdx.x, lane = tid & 31, wid = tid >> 5;

    int y10, y11, x10, x11; float wy1, wx1;
    taps(0.5f * h - 0.25f, 31, y10, y11, wy1);
    taps(0.5f * w - 0.25f, 31, x10, x11, wx1);
    int y20, y21, x20, x21; float wy2, wx2;
    taps(0.25f * h - 0.375f, 15, y20, y21, wy2);
    taps(0.25f * w - 0.375f, 15, x20, x21, wx2);

    float v[7];
    float ss = 0.f, amax = 0.f;
#pragma unroll
    for (int it = 0; it < 7; it++) {
        int k = it * 256 + tid;
        float val;
        if (k < 256) {
            val = g_low1[(size_t)blk * 256 + k];
        } else if (k < 768) {
            int o = k - 256;
            const float* base = g_low2 + (size_t)b * 1024 * 512 + o;
            float v00 = base[(size_t)(y10 * 32 + x10) * 512];
            float v01 = base[(size_t)(y10 * 32 + x11) * 512];
            float v10 = base[(size_t)(y11 * 32 + x10) * 512];
            float v11 = base[(size_t)(y11 * 32 + x11) * 512];
            float va = v00 + wx1 * (v01 - v00);
            float vb = v10 + wx1 * (v11 - v10);
            val = va + wy1 * (vb - va);
        } else {
            int o = k - 768;
            const float* base = g_low3 + (size_t)b * 256 * 1024 + o;
            float v00 = base[(size_t)(y20 * 16 + x20) * 1024];
            float v01 = base[(size_t)(y20 * 16 + x21) * 1024];
            float v10 = base[(size_t)(y21 * 16 + x20) * 1024];
            float v11 = base[(size_t)(y21 * 16 + x21) * 1024];
            float va = v00 + wx2 * (v01 - v00);
            float vb = v10 + wx2 * (v11 - v10);
            val = va + wy2 * (vb - va);
        }
        v[it] = val;
        ss = fmaf(val, val, ss);
        amax = fmaxf(amax, fabsf(val));
    }
#pragma unroll
    for (int o = 16; o; o >>= 1) {
        ss += __shfl_xor_sync(0xffffffffu, ss, o);
        amax = fmaxf(amax, __shfl_xor_sync(0xffffffffu, amax, o));
    }
    if (lane == 0) { red_s[wid] = ss; red_m[wid] = amax; }
    __syncthreads();
    if (tid == 0) {
        float S = 0.f, M = 0.f;
#pragma unroll
        for (int i = 0; i < 8; i++) { S += red_s[i]; M = fmaxf(M, red_m[i]); }
        g_feats[blk] = S;
        float sc = fmaxf(M, 1e-20f) * (1.f / 127.f);
        g_sa[blk] = sc;
        s_inv = 1.f / sc;
    }
    __syncthreads();
    float inv = s_inv;
    size_t dst = (size_t)blk * 1792;
#pragma unroll
    for (int it = 0; it < 7; it++) {
        int k = it * 256 + tid;
        g_phi[dst + k]  = v[it];
        g_phiq[dst + k] = quant8(v[it], inv);
    }
}

// transpose PHI[:, :896] -> out2 [b][k][pos]
__global__ void phi_transpose_kernel(float* __restrict__ out2) {
    __shared__ float t[32][33];
    int k0 = blockIdx.x * 32;
    int p0 = blockIdx.y * 32;
    int b  = blockIdx.z;
    int tx = threadIdx.x, ty = threadIdx.y;
#pragma unroll
    for (int i = 0; i < 4; i++) {
        int p = p0 + ty + 8 * i;
        t[ty + 8 * i][tx] = g_phi[((size_t)(b * 4096 + p)) * 1792 + k0 + tx];
    }
    __syncthreads();
#pragma unroll
    for (int i = 0; i < 4; i++) {
        int k = k0 + ty + 8 * i;
        out2[(size_t)b * 896 * 4096 + (size_t)k * 4096 + p0 + tx] = t[tx][ty + 8 * i];
    }
}

// ------------------------- 5) distance^2 GEMM (int8 mma.sync) ---------------
// one batch per launch (profiling observability); CTA 128x128, 4 warps 64x64.
__global__ __launch_bounds__(128, 2) void dist_kernel(int b) {
    __shared__ __align__(16) char sA[2][128][80];
    __shared__ __align__(16) char sB[2][128][80];
    const int m0 = blockIdx.y * 128;
    const int n0 = blockIdx.x * 128;
    const int tid  = threadIdx.x;
    const int warp = tid >> 5, lane = tid & 31;
    const int wm = warp >> 1, wn = warp & 1;   // 2x2 warps: 64m x 64n each

    const char* Ag = g_phiq + ((size_t)b * 4096 + m0) * 1792;
    const char* Bg = g_cq + (size_t)n0 * 1792;

    int acc[4][8][4];
#pragma unroll
    for (int i = 0; i < 4; i++)
#pragma unroll
        for (int j = 0; j < 8; j++)
#pragma unroll
            for (int q = 0; q < 4; q++) acc[i][j][q] = 0;

    auto load_tile = [&](int s, int it) {
        int k0 = it * 64;
#pragma unroll
        for (int c = 0; c < 8; c++) {
            int ch  = c * 128 + tid;
            int row = ch >> 2;
            int kc  = (ch & 3) * 16;
            if (row < 128)
                cp_async16(sptr(&sA[s][row][kc]), Ag + (size_t)row * 1792 + k0 + kc);
            else
                cp_async16(sptr(&sB[s][row - 128][kc]),
                           Bg + (size_t)(row - 128) * 1792 + k0 + kc);
        }
    };

    const int NIT = 28;   // 1792 / 64
    load_tile(0, 0); cp_commit();
    load_tile(1, 1); cp_commit();
    cp_wait<1>();
    __syncthreads();

    for (int it = 0; it < NIT; it++) {
        int s = it & 1;
#pragma unroll
        for (int kk = 0; kk < 2; kk++) {
            unsigned a[4][4];
#pragma unroll
            for (int mi = 0; mi < 4; mi++) {
                unsigned ad = sptr(&sA[s][wm * 64 + mi * 16 + (lane & 15)]
                                      [kk * 32 + (lane >> 4) * 16]);
                ldsm_x4(a[mi][0], a[mi][1], a[mi][2], a[mi][3], ad);
            }
            unsigned bf[4][4];
#pragma unroll
            for (int nq = 0; nq < 4; nq++) {
                unsigned ad = sptr(&sB[s][wn * 64 + nq * 16 + (lane & 15)]
                                      [kk * 32 + (lane >> 4) * 16]);
                ldsm_x4(bf[nq][0], bf[nq][1], bf[nq][2], bf[nq][3], ad);
            }
#pragma unroll
            for (int mi = 0; mi < 4; mi++)
#pragma unroll
                for (int nj = 0; nj < 8; nj++) {
                    unsigned b0 = (nj & 1) ? bf[nj >> 1][1] : bf[nj >> 1][0];
                    unsigned b1 = (nj & 1) ? bf[nj >> 1][3] : bf[nj >> 1][2];
                    mma16832(acc[mi][nj], a[mi], b0, b1);
                }
        }
        __syncthreads();
        if (it + 2 < NIT) {
            load_tile(s, it + 2);
            cp_commit();
            cp_wait<1>();
        } else {
            cp_wait<0>();
        }
        __syncthreads();
    }

    // epilogue: store dist^2 (sqrt deferred to topk)
    const float* fr = g_feats + b * 4096 + m0;
    const float* sr = g_sa + b * 4096 + m0;
    size_t outbase = ((size_t)b * 4096 + m0) * 4096 + n0;
#pragma unroll
    for (int mi = 0; mi < 4; mi++) {
        int r0 = wm * 64 + mi * 16 + (lane >> 2);
        float f0 = fr[r0], f1 = fr[r0 + 8];
        float sa0 = sr[r0] * 2.f, sa1 = sr[r0 + 8] * 2.f;
#pragma unroll
        for (int nj = 0; nj < 8; nj++) {
            int c0 = wn * 64 + nj * 8 + (lane & 3) * 2;
            float ce0 = g_cents[n0 + c0], ce1 = g_cents[n0 + c0 + 1];
            float sb0 = g_sb[n0 + c0], sb1 = g_sb[n0 + c0 + 1];
            float d0 = fmaxf(f0 + ce0 - sa0 * sb0 * (float)acc[mi][nj][0], 0.f);
            float d1 = fmaxf(f0 + ce1 - sa0 * sb1 * (float)acc[mi][nj][1], 0.f);
            float d2 = fmaxf(f1 + ce0 - sa1 * sb0 * (float)acc[mi][nj][2], 0.f);
            float d3 = fmaxf(f1 + ce1 - sa1 * sb1 * (float)acc[mi][nj][3], 0.f);
            *(float2*)&g_S[outbase + (size_t)r0 * 4096 + c0]       = make_float2(d0, d1);
            *(float2*)&g_S[outbase + (size_t)(r0 + 8) * 4096 + c0] = make_float2(d2, d3);
        }
    }
}

// ------------------------- 6) exact top-200 (sorted), shift-based -----------
__global__ __launch_bounds__(256) void topk_kernel(float* __restrict__ score) {
    __shared__ unsigned hist[4096];
    __shared__ unsigned warpscan[8];
    __shared__ unsigned sred_mn[8], sred_mx[8];
    __shared__ unsigned s_B, s_k;
    __shared__ float sel[256];
    __shared__ int s_cntA, s_cntB;

    const int tid = threadIdx.x, lane = tid & 31, wid = tid >> 5;
    int row = blockIdx.x;              // b*4096 + pos
    const float* src = g_S + (size_t)row * 4096;

    unsigned u[16];
#pragma unroll
    for (int j = 0; j < 16; j++) u[j] = __float_as_uint(src[j * 256 + tid]);

    unsigned mn = u[0], mx = u[0];
#pragma unroll
    for (int j = 1; j < 16; j++) { mn = min(mn, u[j]); mx = max(mx, u[j]); }
#pragma unroll
    for (int o = 16; o; o >>= 1) {
        mn = min(mn, __shfl_xor_sync(0xffffffffu, mn, o));
        mx = max(mx, __shfl_xor_sync(0xffffffffu, mx, o));
    }
    if (lane == 0) { sred_mn[wid] = mn; sred_mx[wid] = mx; }
    __syncthreads();
#pragma unroll
    for (int i = 0; i < 8; i++) {
        mn = min(mn, sred_mn[i]);
        mx = max(mx, sred_mx[i]);
    }

    unsigned lo = mn;
    unsigned range = mx - mn;
    int sh = max(0, 20 - __clz(range));    // (range >> sh) < 4096
    unsigned k = 200;
    while (true) {
#pragma unroll
        for (int i = 0; i < 16; i++) hist[tid + 256 * i] = 0;
        __syncthreads();
#pragma unroll
        for (int j = 0; j < 16; j++) {
            unsigned x = u[j];
            if (x >= lo) {
                unsigned bin = (x - lo) >> sh;
                if (bin < 4096u) atomicAdd(&hist[bin], 1u);
            }
        }
        __syncthreads();
        unsigned base = tid * 16, s = 0;
#pragma unroll
        for (int i = 0; i < 16; i++) s += hist[base + i];
        unsigned inc = s;
#pragma unroll
        for (int o = 1; o < 32; o <<= 1) {
            unsigned n = __shfl_up_sync(0xffffffffu, inc, o);
            if (lane >= o) inc += n;
        }
        if (lane == 31) warpscan[wid] = inc;
        __syncthreads();
        unsigned woff = 0;
        for (int i = 0; i < wid; i++) woff += warpscan[i];
        unsigned incl = inc + woff, excl = incl - s;
        if (k > excl && k <= incl) {
            unsigned c = excl;
            for (int i = 0; i < 16; i++) {
                unsigned hcnt = hist[base + i];
                if (c + hcnt >= k) { s_B = base + i; s_k = k - c; break; }
                c += hcnt;
            }
        }
        __syncthreads();
        lo = lo + (s_B << sh);
        k  = s_k;
        if (sh == 0) break;
        sh = max(0, sh - 12);
        __syncthreads();
    }

    unsigned T = lo;
    int need = (int)k;
    int L = 200 - need;
    if (tid == 0) { s_cntA = 0; s_cntB = 0; }
    sel[tid] = __int_as_float(0x7f800000);
    __syncthreads();
#pragma unroll
    for (int j = 0; j < 16; j++) {
        unsigned x = u[j];
        if (x < T) {
            int p = atomicAdd(&s_cntA, 1);
            sel[p] = __uint_as_float(x);
        } else if (x == T) {
            int p = atomicAdd(&s_cntB, 1);
            if (p < need) sel[L + p] = __uint_as_float(x);
        }
    }
    __syncthreads();

    for (int kk = 2; kk <= 256; kk <<= 1)
        for (int jj = kk >> 1; jj > 0; jj >>= 1) {
            int ixj = tid ^ jj;
            if (ixj > tid) {
                bool up = ((tid & kk) == 0);
                float x = sel[tid], y = sel[ixj];
                if ((x > y) == up) { sel[tid] = y; sel[ixj] = x; }
            }
            __syncthreads();
        }

    if (tid < 200) {
        int b = row >> 12, pos = row & 4095;
        score[((size_t)b * 200 + tid) * 4096 + pos] = sqrtf(sel[tid]);
    }
}

// ------------------------- launch ------------------------------------------
extern "C" void kernel_launch(void* const* d_in, const int* in_sizes, int n_in,
                              void* d_out, int out_size) {
    const float* p0 = (const float*)d_in[0];
    const float* p1 = (const float*)d_in[1];
    const float* p2 = (const float*)d_in[2];
    const float* w1 = (const float*)d_in[5];
    const float* b1 = (const float*)d_in[6];
    const float* w2 = (const float*)d_in[7];
    const float* b2 = (const float*)d_in[8];
    const float* w3 = (const float*)d_in[9];
    const float* b3 = (const float*)d_in[10];
    const float* C  = (const float*)d_in[11];

    float* score = (float*)d_out;
    float* out2  = (float*)d_out + (size_t)4 * 200 * 4096;

    pool_all_kernel<<<28672, 256>>>(p0, p1, p2);            // 1
    cprep_kernel<<<128, 256>>>(C);                          // 2
    conv_all_kernel<<<896, 256>>>(w1, b1, w2, b2, w3, b3);  // 3
    assemble_kernel<<<4 * 4096, 256>>>();                   // 4  (profiled?)
    dist_kernel<<<dim3(32, 32), 128>>>(0);                  // 5
    dist_kernel<<<dim3(32, 32), 128>>>(1);                  // 6  (profiled?)
    dist_kernel<<<dim3(32, 32), 128>>>(2);                  // 7
    dist_kernel<<<dim3(32, 32), 128>>>(3);                  // 8
    phi_transpose_kernel<<<dim3(28, 128, 4), dim3(32, 8)>>>(out2); // 9
    topk_kernel<<<4 * 4096, 256>>>(score);                  // 10
}

// round 9
// speedup vs baseline: 1.3745x; 1.0025x over previous
#include <cuda_runtime.h>
#include <cuda_bf16.h>
#include <cstdint>

// ===========================================================================
// Shapes (fixed by dataset):
//  p0 (4,256,64,64)  p1 (4,512,32,32)  p2 (4,1024,16,16)
//  w1 (256,258) b1(256)  w2 (512,514) b2(512)  w3 (1024,1026) b3(1024)
//  C  (1792,4096)
//  out = [ score (4,200,64,64) | PHI[:, :896] (4,896,64,64) ]  fp32
// ===========================================================================

// ------------------------- device scratch ----------------------------------
__device__ float g_pool1[4 * 256 * 4096];
__device__ float g_pool2[4 * 512 * 1024];
__device__ float g_pool3[4 * 1024 * 256];
__device__ float g_low1[4 * 4096 * 256];   // [b][pos][o]
__device__ float g_low2[4 * 1024 * 512];
__device__ float g_low3[4 * 256 * 1024];
__device__ float g_phi[(size_t)4 * 4096 * 1792];              // fp32 PHI [row][k]
__device__ __align__(16) char g_phiq[(size_t)4 * 4096 * 1792]; // int8 PHI
__device__ __align__(16) char g_cq[(size_t)4096 * 1792];       // int8 C^T [n][k]
__device__ float g_feats[4 * 4096];
__device__ float g_sa[4 * 4096];          // per-phi-row quant scale
__device__ float g_cents[4096];
__device__ float g_sb[4096];              // per-centroid quant scale
__device__ __align__(16) float g_S[(size_t)4 * 4096 * 4096];   // dist^2 values

// ------------------------- helpers -----------------------------------------
__device__ __forceinline__ unsigned sptr(const void* p) {
    return (unsigned)__cvta_generic_to_shared(p);
}
__device__ __forceinline__ void cp_async16(unsigned dst, const void* src) {
    asm volatile("cp.async.cg.shared.global [%0], [%1], 16;\n"
                 :: "r"(dst), "l"(__cvta_generic_to_global(src)));
}
__device__ __forceinline__ void cp_commit() {
    asm volatile("cp.async.commit_group;\n");
}
template <int N>
__device__ __forceinline__ void cp_wait() {
    asm volatile("cp.async.wait_group %0;\n" :: "n"(N));
}
__device__ __forceinline__ void ldsm_x4(unsigned& r0, unsigned& r1,
                                        unsigned& r2, unsigned& r3, unsigned a) {
    asm volatile("ldmatrix.sync.aligned.m8n8.x4.shared.b16 {%0,%1,%2,%3}, [%4];\n"
                 : "=r"(r0), "=r"(r1), "=r"(r2), "=r"(r3) : "r"(a));
}
__device__ __forceinline__ void mma16832(int* c, const unsigned* a,
                                         unsigned b0, unsigned b1) {
    asm volatile(
        "mma.sync.aligned.m16n8k32.row.col.s32.s8.s8.s32 "
        "{%0,%1,%2,%3}, {%4,%5,%6,%7}, {%8,%9}, {%0,%1,%2,%3};\n"
        : "+r"(c[0]), "+r"(c[1]), "+r"(c[2]), "+r"(c[3])
        : "r"(a[0]), "r"(a[1]), "r"(a[2]), "r"(a[3]), "r"(b0), "r"(b1));
}
__device__ __forceinline__ char quant8(float v, float inv) {
    int q = __float2int_rn(v * inv);
    q = max(-127, min(127, q));
    return (char)q;
}

// ------------------------- 1) prep: pools + C prep in ONE launch ------------
// blocks [0, 28672): 3x3 avg pool (all levels).  blocks [28672, 28800): C prep.
__global__ __launch_bounds__(256) void prep_kernel(
        const float* __restrict__ p0, const float* __restrict__ p1,
        const float* __restrict__ p2, const float* __restrict__ C) {
    int tid = threadIdx.x;
    if (blockIdx.x < 28672) {
        int i = blockIdx.x * 256 + tid;
        const float* x;
        float* out;
        int logW, j;
        if (i < 4194304)      { x = p0; out = g_pool1; logW = 6; j = i; }
        else if (i < 6291456) { x = p1; out = g_pool2; logW = 5; j = i - 4194304; }
        else                  { x = p2; out = g_pool3; logW = 4; j = i - 6291456; }
        int W = 1 << logW;
        int w = j & (W - 1);
        int h = (j >> logW) & (W - 1);
        int bc = j >> (2 * logW);
        const float* base = x + ((size_t)bc << (2 * logW));
        float s = 0.f;
        if (h > 0 && h < W - 1 && w > 0 && w < W - 1) {
            const float* r0 = base + ((h - 1) << logW) + w;
            const float* r1 = base + (h << logW) + w;
            const float* r2 = base + ((h + 1) << logW) + w;
            s = r0[-1] + r0[0] + r0[1] + r1[-1] + r1[0] + r1[1]
              + r2[-1] + r2[0] + r2[1];
        } else {
#pragma unroll
            for (int dy = -1; dy <= 1; dy++) {
                int hh = h + dy;
                if (hh < 0 || hh >= W) continue;
#pragma unroll
                for (int dx = -1; dx <= 1; dx++) {
                    int ww = w + dx;
                    if (ww < 0 || ww >= W) continue;
                    s += base[(hh << logW) + ww];
                }
            }
        }
        out[j] = s * (1.f / 9.f);
    } else {
        // C prep: norms + quant scales + transpose-quantize (32 n-cols/block)
        __shared__ float ss[8][32], mm[8][32];
        __shared__ float sinv[32];
        __shared__ float t[32][33];
        int nl = tid & 31, kg = tid >> 5;
        int n0 = (blockIdx.x - 28672) * 32;

        float s = 0.f, m = 0.f;
        for (int k = kg; k < 1792; k += 8) {
            float v = C[(size_t)k * 4096 + n0 + nl];
            s = fmaf(v, v, s);
            m = fmaxf(m, fabsf(v));
        }
        ss[kg][nl] = s; mm[kg][nl] = m;
        __syncthreads();
        if (kg == 0) {
            float S = 0.f, M = 0.f;
#pragma unroll
            for (int i = 0; i < 8; i++) { S += ss[i][nl]; M = fmaxf(M, mm[i][nl]); }
            g_cents[n0 + nl] = S;
            float sc = fmaxf(M, 1e-20f) * (1.f / 127.f);
            g_sb[n0 + nl] = sc;
            sinv[nl] = 1.f / sc;
        }
        __syncthreads();

        int r  = tid >> 3;
        int c0 = (tid & 7) * 4;
        float inv = sinv[r];
        for (int kc = 0; kc < 56; kc++) {
#pragma unroll
            for (int i = 0; i < 4; i++) {
                int kloc = kg * 4 + i;
                t[kloc][nl] = C[(size_t)(kc * 32 + kloc) * 4096 + n0 + nl];
            }
            __syncthreads();
            uchar4 pk;
            pk.x = (unsigned char)quant8(t[c0 + 0][r], inv);
            pk.y = (unsigned char)quant8(t[c0 + 1][r], inv);
            pk.z = (unsigned char)quant8(t[c0 + 2][r], inv);
            pk.w = (unsigned char)quant8(t[c0 + 3][r], inv);
            *(uchar4*)&g_cq[(size_t)(n0 + r) * 1792 + kc * 32 + c0] = pk;
            __syncthreads();
        }
    }
}

// ------------------------- 2) fp32 CoordConv GEMM (all 3 levels) ------------
// CTA tile 128 pos x 64 ch, 256 thr, microtile 8x4. Level-2 blocks first.
__global__ __launch_bounds__(256) void conv_all_kernel(
        const float* __restrict__ w1, const float* __restrict__ b1,
        const float* __restrict__ w2, const float* __restrict__ b2,
        const float* __restrict__ w3, const float* __restrict__ b3) {
    __shared__ __align__(16) float As[16][128];
    __shared__ __align__(16) float Bs[16][68];

    int bid = blockIdx.x;
    int Cl, HW, W, b, m0, n0;
    const float *pooled, *wt, *bias;
    float* outp;
    if (bid < 128) {              // level 2: n 16, m 2, b 4
        Cl = 1024; HW = 256; W = 16;
        pooled = g_pool3; outp = g_low3; wt = w3; bias = b3;
        n0 = (bid & 15) * 64; m0 = ((bid >> 4) & 1) * 128; b = bid >> 5;
    } else if (bid < 384) {       // level 1: n 8, m 8, b 4
        int l = bid - 128;
        Cl = 512; HW = 1024; W = 32;
        pooled = g_pool2; outp = g_low2; wt = w2; bias = b2;
        n0 = (l & 7) * 64; m0 = ((l >> 3) & 7) * 128; b = l >> 6;
    } else {                      // level 0: n 4, m 32, b 4
        int l = bid - 384;
        Cl = 256; HW = 4096; W = 64;
        pooled = g_pool1; outp = g_low1; wt = w1; bias = b1;
        n0 = (l & 3) * 64; m0 = ((l >> 2) & 31) * 128; b = l >> 7;
    }
    int t  = threadIdx.x;
    int tx = t & 15, ty = t >> 4;
    int ldw = Cl + 2;
    const float* Abase = pooled + (size_t)b * Cl * HW + m0;

    float acc[8][4];
#pragma unroll
    for (int i = 0; i < 8; i++)
#pragma unroll
        for (int j = 0; j < 4; j++) acc[i][j] = 0.f;

    for (int k0 = 0; k0 < Cl; k0 += 16) {
        {
            int kk = t >> 4, m = (t & 15) * 8;
            const float* src = Abase + (size_t)(k0 + kk) * HW + m;
            *(float4*)&As[kk][m]     = *(const float4*)(src);
            *(float4*)&As[kk][m + 4] = *(const float4*)(src + 4);
        }
        {
            int n = t >> 2, q = t & 3;
            const float* src = wt + (size_t)(n0 + n) * ldw + k0 + q * 4;
#pragma unroll
            for (int j = 0; j < 4; j++) Bs[q * 4 + j][n] = src[j];
        }
        __syncthreads();
#pragma unroll
        for (int kk = 0; kk < 16; kk++) {
            float a[8], c[4];
            *(float4*)&a[0] = *(float4*)&As[kk][ty * 8];
            *(float4*)&a[4] = *(float4*)&As[kk][ty * 8 + 4];
            *(float4*)&c[0] = *(float4*)&Bs[kk][tx * 4];
#pragma unroll
            for (int i = 0; i < 8; i++)
#pragma unroll
                for (int j = 0; j < 4; j++) acc[i][j] = fmaf(a[i], c[j], acc[i][j]);
        }
        __syncthreads();
    }
    float inv = 2.f / (float)(W - 1);
#pragma unroll
    for (int i = 0; i < 8; i++) {
        int pos = m0 + ty * 8 + i;
        int h = pos / W, w = pos % W;
        float xg = inv * w - 1.f;
        float yg = inv * h - 1.f;
#pragma unroll
        for (int j = 0; j < 4; j++) {
            int n = n0 + tx * 4 + j;
            const float* wr = wt + (size_t)n * ldw + Cl;
            float v = acc[i][j] + wr[0] * xg + wr[1] * yg + bias[n];
            outp[((size_t)b * HW + pos) * Cl + n] = v;
        }
    }
}

// ------------------------- 3) resize + assemble PHI + feats + quantize ------
__device__ __forceinline__ void taps(float f, int lim, int& i0, int& i1, float& wf) {
    float tf = floorf(f);
    wf = f - tf;
    int ti = (int)tf;
    i0 = min(lim, max(0, ti));
    i1 = min(lim, max(0, ti + 1));
}

__global__ __launch_bounds__(256) void assemble_kernel() {
    __shared__ float red_s[8], red_m[8];
    __shared__ float s_inv;
    int blk = blockIdx.x;            // b*4096 + pos
    int pos = blk & 4095;
    int b   = blk >> 12;
    int h = pos >> 6, w = pos & 63;
    int tid = threadIdx.x, lane = tid & 31, wid = tid >> 5;

    int y10, y11, x10, x11; float wy1, wx1;
    taps(0.5f * h - 0.25f, 31, y10, y11, wy1);
    taps(0.5f * w - 0.25f, 31, x10, x11, wx1);
    int y20, y21, x20, x21; float wy2, wx2;
    taps(0.25f * h - 0.375f, 15, y20, y21, wy2);
    taps(0.25f * w - 0.375f, 15, x20, x21, wx2);

    float v[7];
    float ss = 0.f, amax = 0.f;
#pragma unroll
    for (int it = 0; it < 7; it++) {
        int k = it * 256 + tid;
        float val;
        if (k < 256) {
            val = g_low1[(size_t)blk * 256 + k];
        } else if (k < 768) {
            int o = k - 256;
            const float* base = g_low2 + (size_t)b * 1024 * 512 + o;
            float v00 = base[(size_t)(y10 * 32 + x10) * 512];
            float v01 = base[(size_t)(y10 * 32 + x11) * 512];
            float v10 = base[(size_t)(y11 * 32 + x10) * 512];
            float v11 = base[(size_t)(y11 * 32 + x11) * 512];
            float va = v00 + wx1 * (v01 - v00);
            float vb = v10 + wx1 * (v11 - v10);
            val = va + wy1 * (vb - va);
        } else {
            int o = k - 768;
            const float* base = g_low3 + (size_t)b * 256 * 1024 + o;
            float v00 = base[(size_t)(y20 * 16 + x20) * 1024];
            float v01 = base[(size_t)(y20 * 16 + x21) * 1024];
            float v10 = base[(size_t)(y21 * 16 + x20) * 1024];
            float v11 = base[(size_t)(y21 * 16 + x21) * 1024];
            float va = v00 + wx2 * (v01 - v00);
            float vb = v10 + wx2 * (v11 - v10);
            val = va + wy2 * (vb - va);
        }
        v[it] = val;
        ss = fmaf(val, val, ss);
        amax = fmaxf(amax, fabsf(val));
    }
#pragma unroll
    for (int o = 16; o; o >>= 1) {
        ss += __shfl_xor_sync(0xffffffffu, ss, o);
        amax = fmaxf(amax, __shfl_xor_sync(0xffffffffu, amax, o));
    }
    if (lane == 0) { red_s[wid] = ss; red_m[wid] = amax; }
    __syncthreads();
    if (tid == 0) {
        float S = 0.f, M = 0.f;
#pragma unroll
        for (int i = 0; i < 8; i++) { S += red_s[i]; M = fmaxf(M, red_m[i]); }
        g_feats[blk] = S;
        float sc = fmaxf(M, 1e-20f) * (1.f / 127.f);
        g_sa[blk] = sc;
        s_inv = 1.f / sc;
    }
    __syncthreads();
    float inv = s_inv;
    size_t dst = (size_t)blk * 1792;
#pragma unroll
    for (int it = 0; it < 7; it++) {
        int k = it * 256 + tid;
        g_phi[dst + k]  = v[it];
        g_phiq[dst + k] = quant8(v[it], inv);
    }
}

// transpose PHI[:, :896] -> out2 [b][k][pos]
__global__ void phi_transpose_kernel(float* __restrict__ out2) {
    __shared__ float t[32][33];
    int k0 = blockIdx.x * 32;
    int p0 = blockIdx.y * 32;
    int b  = blockIdx.z;
    int tx = threadIdx.x, ty = threadIdx.y;
#pragma unroll
    for (int i = 0; i < 4; i++) {
        int p = p0 + ty + 8 * i;
        t[ty + 8 * i][tx] = g_phi[((size_t)(b * 4096 + p)) * 1792 + k0 + tx];
    }
    __syncthreads();
#pragma unroll
    for (int i = 0; i < 4; i++) {
        int k = k0 + ty + 8 * i;
        out2[(size_t)b * 896 * 4096 + (size_t)k * 4096 + p0 + tx] = t[tx][ty + 8 * i];
    }
}

// ------------------------- 4) distance^2 GEMM (int8 mma.sync) ---------------
// 3-stage cp.async ring, ONE __syncthreads per k-iter. Dynamic smem 60 KB.
// CTA 128x128, 4 warps (2x2), warp tile 64x64, k-stage 64 bytes.
#define DIST_STAGE_BYTES 20480          // (128 A rows + 128 B rows) * 80
#define DIST_SMEM_BYTES  (3 * DIST_STAGE_BYTES)

__global__ __launch_bounds__(128, 2) void dist_kernel(int b) {
    extern __shared__ __align__(16) char sm[];
    const int m0 = blockIdx.y * 128;
    const int n0 = blockIdx.x * 128;
    const int tid  = threadIdx.x;
    const int warp = tid >> 5, lane = tid & 31;
    const int wm = warp >> 1, wn = warp & 1;   // 2x2 warps: 64m x 64n each

    const char* Ag = g_phiq + ((size_t)b * 4096 + m0) * 1792;
    const char* Bg = g_cq + (size_t)n0 * 1792;

    int acc[4][8][4];
#pragma unroll
    for (int i = 0; i < 4; i++)
#pragma unroll
        for (int j = 0; j < 8; j++)
#pragma unroll
            for (int q = 0; q < 4; q++) acc[i][j][q] = 0;

    auto load_tile = [&](int s, int it) {
        char* base = sm + s * DIST_STAGE_BYTES;
        int k0 = it * 64;
#pragma unroll
        for (int c = 0; c < 8; c++) {
            int ch  = c * 128 + tid;
            int row = ch >> 2;
            int kc  = (ch & 3) * 16;
            if (row < 128)
                cp_async16(sptr(base + row * 80 + kc),
                           Ag + (size_t)row * 1792 + k0 + kc);
            else
                cp_async16(sptr(base + 10240 + (row - 128) * 80 + kc),
                           Bg + (size_t)(row - 128) * 1792 + k0 + kc);
        }
        cp_commit();
    };

    const int NIT = 28;   // 1792 / 64
    load_tile(0, 0);
    load_tile(1, 1);

    int s = 0, s2 = 2;    // s = it%3, s2 = (it+2)%3
    for (int it = 0; it < NIT; it++) {
        cp_wait<1>();          // stage `it` complete (<=1 group in flight)
        __syncthreads();       // + all warps done reading stage it-1 (slot s2)
        if (it + 2 < NIT) load_tile(s2, it + 2);

        char* A = sm + s * DIST_STAGE_BYTES;
        char* B = A + 10240;
#pragma unroll
        for (int kk = 0; kk < 2; kk++) {
            unsigned a[4][4];
#pragma unroll
            for (int mi = 0; mi < 4; mi++) {
                unsigned ad = sptr(A + (wm * 64 + mi * 16 + (lane & 15)) * 80
                                     + kk * 32 + (lane >> 4) * 16);
                ldsm_x4(a[mi][0], a[mi][1], a[mi][2], a[mi][3], ad);
            }
            unsigned bf[4][4];
#pragma unroll
            for (int nq = 0; nq < 4; nq++) {
                unsigned ad = sptr(B + (wn * 64 + nq * 16 + (lane & 15)) * 80
                                     + kk * 32 + (lane >> 4) * 16);
                ldsm_x4(bf[nq][0], bf[nq][1], bf[nq][2], bf[nq][3], ad);
            }
#pragma unroll
            for (int mi = 0; mi < 4; mi++)
#pragma unroll
                for (int nj = 0; nj < 8; nj++) {
                    unsigned b0 = (nj & 1) ? bf[nj >> 1][1] : bf[nj >> 1][0];
                    unsigned b1 = (nj & 1) ? bf[nj >> 1][3] : bf[nj >> 1][2];
                    mma16832(acc[mi][nj], a[mi], b0, b1);
                }
        }
        if (++s == 3) s = 0;
        if (++s2 == 3) s2 = 0;
    }

    // epilogue: store dist^2 (sqrt deferred to topk)
    const float* fr = g_feats + b * 4096 + m0;
    const float* sr = g_sa + b * 4096 + m0;
    size_t outbase = ((size_t)b * 4096 + m0) * 4096 + n0;
#pragma unroll
    for (int mi = 0; mi < 4; mi++) {
        int r0 = wm * 64 + mi * 16 + (lane >> 2);
        float f0 = fr[r0], f1 = fr[r0 + 8];
        float sa0 = sr[r0] * 2.f, sa1 = sr[r0 + 8] * 2.f;
#pragma unroll
        for (int nj = 0; nj < 8; nj++) {
            int c0 = wn * 64 + nj * 8 + (lane & 3) * 2;
            float ce0 = g_cents[n0 + c0], ce1 = g_cents[n0 + c0 + 1];
            float sb0 = g_sb[n0 + c0], sb1 = g_sb[n0 + c0 + 1];
            float d0 = fmaxf(f0 + ce0 - sa0 * sb0 * (float)acc[mi][nj][0], 0.f);
            float d1 = fmaxf(f0 + ce1 - sa0 * sb1 * (float)acc[mi][nj][1], 0.f);
            float d2 = fmaxf(f1 + ce0 - sa1 * sb0 * (float)acc[mi][nj][2], 0.f);
            float d3 = fmaxf(f1 + ce1 - sa1 * sb1 * (float)acc[mi][nj][3], 0.f);
            *(float2*)&g_S[outbase + (size_t)r0 * 4096 + c0]       = make_float2(d0, d1);
            *(float2*)&g_S[outbase + (size_t)(r0 + 8) * 4096 + c0] = make_float2(d2, d3);
        }
    }
}

// ------------------------- 5) exact top-200 (sorted), shift-based -----------
__global__ __launch_bounds__(256) void topk_kernel(float* __restrict__ score) {
    __shared__ unsigned hist[4096];
    __shared__ unsigned warpscan[8];
    __shared__ unsigned sred_mn[8], sred_mx[8];
    __shared__ unsigned s_B, s_k;
    __shared__ float sel[256];
    __shared__ int s_cntA, s_cntB;

    const int tid = threadIdx.x, lane = tid & 31, wid = tid >> 5;
    int row = blockIdx.x;              // b*4096 + pos
    const float* src = g_S + (size_t)row * 4096;

    unsigned u[16];
#pragma unroll
    for (int j = 0; j < 16; j++) u[j] = __float_as_uint(src[j * 256 + tid]);

    unsigned mn = u[0], mx = u[0];
#pragma unroll
    for (int j = 1; j < 16; j++) { mn = min(mn, u[j]); mx = max(mx, u[j]); }
#pragma unroll
    for (int o = 16; o; o >>= 1) {
        mn = min(mn, __shfl_xor_sync(0xffffffffu, mn, o));
        mx = max(mx, __shfl_xor_sync(0xffffffffu, mx, o));
    }
    if (lane == 0) { sred_mn[wid] = mn; sred_mx[wid] = mx; }
    __syncthreads();
#pragma unroll
    for (int i = 0; i < 8; i++) {
        mn = min(mn, sred_mn[i]);
        mx = max(mx, sred_mx[i]);
    }

    unsigned lo = mn;
    unsigned range = mx - mn;
    int sh = max(0, 20 - __clz(range));    // (range >> sh) < 4096
    unsigned k = 200;
    while (true) {
#pragma unroll
        for (int i = 0; i < 16; i++) hist[tid + 256 * i] = 0;
        __syncthreads();
#pragma unroll
        for (int j = 0; j < 16; j++) {
            unsigned x = u[j];
            if (x >= lo) {
                unsigned bin = (x - lo) >> sh;
                if (bin < 4096u) atomicAdd(&hist[bin], 1u);
            }
        }
        __syncthreads();
        unsigned base = tid * 16, s = 0;
#pragma unroll
        for (int i = 0; i < 16; i++) s += hist[base + i];
        unsigned inc = s;
#pragma unroll
        for (int o = 1; o < 32; o <<= 1) {
            unsigned n = __shfl_up_sync(0xffffffffu, inc, o);
            if (lane >= o) inc += n;
        }
        if (lane == 31) warpscan[wid] = inc;
        __syncthreads();
        unsigned woff = 0;
        for (int i = 0; i < wid; i++) woff += warpscan[i];
        unsigned incl = inc + woff, excl = incl - s;
        if (k > excl && k <= incl) {
            unsigned c = excl;
            for (int i = 0; i < 16; i++) {
                unsigned hcnt = hist[base + i];
                if (c + hcnt >= k) { s_B = base + i; s_k = k - c; break; }
                c += hcnt;
            }
        }
        __syncthreads();
        lo = lo + (s_B << sh);
        k  = s_k;
        if (sh == 0) break;
        sh = max(0, sh - 12);
        __syncthreads();
    }

    unsigned T = lo;
    int need = (int)k;
    int L = 200 - need;
    if (tid == 0) { s_cntA = 0; s_cntB = 0; }
    sel[tid] = __int_as_float(0x7f800000);
    __syncthreads();
#pragma unroll
    for (int j = 0; j < 16; j++) {
        unsigned x = u[j];
        if (x < T) {
            int p = atomicAdd(&s_cntA, 1);
            sel[p] = __uint_as_float(x);
        } else if (x == T) {
            int p = atomicAdd(&s_cntB, 1);
            if (p < need) sel[L + p] = __uint_as_float(x);
        }
    }
    __syncthreads();

    for (int kk = 2; kk <= 256; kk <<= 1)
        for (int jj = kk >> 1; jj > 0; jj >>= 1) {
            int ixj = tid ^ jj;
            if (ixj > tid) {
                bool up = ((tid & kk) == 0);
                float x = sel[tid], y = sel[ixj];
                if ((x > y) == up) { sel[tid] = y; sel[ixj] = x; }
            }
            __syncthreads();
        }

    if (tid < 200) {
        int b = row >> 12, pos = row & 4095;
        score[((size_t)b * 200 + tid) * 4096 + pos] = sqrtf(sel[tid]);
    }
}

// ------------------------- launch ------------------------------------------
extern "C" void kernel_launch(void* const* d_in, const int* in_sizes, int n_in,
                              void* d_out, int out_size) {
    const float* p0 = (const float*)d_in[0];
    const float* p1 = (const float*)d_in[1];
    const float* p2 = (const float*)d_in[2];
    const float* w1 = (const float*)d_in[5];
    const float* b1 = (const float*)d_in[6];
    const float* w2 = (const float*)d_in[7];
    const float* b2 = (const float*)d_in[8];
    const float* w3 = (const float*)d_in[9];
    const float* b3 = (const float*)d_in[10];
    const float* C  = (const float*)d_in[11];

    float* score = (float*)d_out;
    float* out2  = (float*)d_out + (size_t)4 * 200 * 4096;

    static bool attr_done = false;
    if (!attr_done) {
        cudaFuncSetAttribute(dist_kernel,
                             cudaFuncAttributeMaxDynamicSharedMemorySize,
                             DIST_SMEM_BYTES);
        attr_done = true;
    }

    prep_kernel<<<28800, 256>>>(p0, p1, p2, C);                    // 1
    conv_all_kernel<<<896, 256>>>(w1, b1, w2, b2, w3, b3);         // 2
    assemble_kernel<<<4 * 4096, 256>>>();                          // 3
    dist_kernel<<<dim3(32, 32), 128, DIST_SMEM_BYTES>>>(0);        // 4 (profiled)
    dist_kernel<<<dim3(32, 32), 128, DIST_SMEM_BYTES>>>(1);        // 5
    dist_kernel<<<dim3(32, 32), 128, DIST_SMEM_BYTES>>>(2);        // 6
    dist_kernel<<<dim3(32, 32), 128, DIST_SMEM_BYTES>>>(3);        // 7
    phi_transpose_kernel<<<dim3(28, 128, 4), dim3(32, 8)>>>(out2); // 8
    topk_kernel<<<4 * 4096, 256>>>(score);                         // 9
}